// round 5
// baseline (speedup 1.0000x reference)
#include <cuda_runtime.h>
#include <cuda_bf16.h>
#include <cstdint>

typedef unsigned long long ull;

// Problem constants
#define BB   4096
#define TT   512
#define INF  3
#define HH   128
#define G4   512   // 4*H

// Persistent-kernel geometry
#define ROWS 32          // batch rows per CTA
#define CTAS (BB/ROWS)   // 128
#define THR  256

// ---------------- device scratch (no cudaMalloc allowed) ----------------
__device__ __align__(16) float g_Wt[HH * G4];  // W_hh transposed: [k][j]  (k-major, 1MB)
__device__ __align__(16) float g_b[G4];        // b_ih + b_hh
__device__ __align__(16) float g_h[BB * HH];   // final hidden state
__device__ float g_scale[HH];
__device__ float g_shift[HH];

// ---------------- f32x2 packed primitives (sm_100 FFMA2 path) ----------------
__device__ __forceinline__ ull f2add(ull a, ull b) {
    ull d; asm("add.rn.f32x2 %0,%1,%2;" : "=l"(d) : "l"(a), "l"(b)); return d;
}
__device__ __forceinline__ ull f2mul(ull a, ull b) {
    ull d; asm("mul.rn.f32x2 %0,%1,%2;" : "=l"(d) : "l"(a), "l"(b)); return d;
}
__device__ __forceinline__ ull f2fma(ull a, ull b, ull c) {
    ull d; asm("fma.rn.f32x2 %0,%1,%2,%3;" : "=l"(d) : "l"(a), "l"(b), "l"(c)); return d;
}
__device__ __forceinline__ ull dup2(float v) {
    ull r; asm("mov.b64 %0,{%1,%1};" : "=l"(r) : "f"(v)); return r;
}
__device__ __forceinline__ float2 unpk(ull a) {
    float2 f; asm("mov.b64 {%0,%1},%2;" : "=f"(f.x), "=f"(f.y) : "l"(a)); return f;
}
__device__ __forceinline__ ull pk(float x, float y) {
    ull r; asm("mov.b64 %0,{%1,%2};" : "=l"(r) : "f"(x), "f"(y)); return r;
}

// ---------------- packed MUFU-free transcendentals ----------------
// 2^t (both lanes), t must be in [-32, 32]
__device__ __forceinline__ ull exp2_2(ull t) {
    ull z  = f2add(t, dup2(12582912.0f));          // round-to-int magic
    ull nf = f2add(z, dup2(-12582912.0f));
    ull f  = f2fma(nf, dup2(-1.0f), t);            // frac in [-0.5,0.5]
    ull p  = f2fma(f, dup2(0.00133335581f), dup2(0.00961812911f));
    p = f2fma(p, f, dup2(0.05550410866f));
    p = f2fma(p, f, dup2(0.24022650700f));
    p = f2fma(p, f, dup2(0.69314718056f));
    p = f2fma(p, f, dup2(1.0f));
    float2 zf = unpk(z), pf = unpk(p);
    float rx = __int_as_float(__float_as_int(pf.x) + ((__float_as_int(zf.x) - 0x4B400000) << 23));
    float ry = __int_as_float(__float_as_int(pf.y) + ((__float_as_int(zf.y) - 0x4B400000) << 23));
    return pk(rx, ry);
}

// 1/d (both lanes), d > 0 normal range. Bit-hack seed + 3 Newton.
__device__ __forceinline__ ull rcp2(ull d) {
    float2 df = unpk(d);
    float sx = __int_as_float(0x7EF477D5 - __float_as_int(df.x));
    float sy = __int_as_float(0x7EF477D5 - __float_as_int(df.y));
    ull y  = pk(sx, sy);
    ull nd = f2mul(d, dup2(-1.0f));
    y = f2mul(y, f2fma(nd, y, dup2(2.0f)));
    y = f2mul(y, f2fma(nd, y, dup2(2.0f)));
    y = f2mul(y, f2fma(nd, y, dup2(2.0f)));
    return y;
}

__device__ __forceinline__ ull clamp2(ull a, float lo, float hi) {
    float2 f = unpk(a);
    f.x = fminf(fmaxf(f.x, lo), hi);
    f.y = fminf(fmaxf(f.y, lo), hi);
    return pk(f.x, f.y);
}

__device__ __forceinline__ ull sigmoid2(ull x) {
    ull t = clamp2(f2mul(x, dup2(-1.44269504089f)), -30.0f, 30.0f);
    return rcp2(f2add(exp2_2(t), dup2(1.0f)));
}
__device__ __forceinline__ ull tanh2(ull x) {
    ull t = clamp2(f2mul(x, dup2(2.88539008178f)), -30.0f, 30.0f);
    ull r = rcp2(f2add(exp2_2(t), dup2(1.0f)));
    return f2fma(r, dup2(-2.0f), dup2(1.0f));
}

// scalar versions for the tiny epilogue
__device__ __forceinline__ float fast_exp2s(float t) {
    float z  = __fadd_rn(t, 12582912.0f);
    int   ni = __float_as_int(z);
    float nf = __fsub_rn(z, 12582912.0f);
    float f  = t - nf;
    float p  = 0.00133335581f;
    p = __fmaf_rn(p, f, 0.00961812911f);
    p = __fmaf_rn(p, f, 0.05550410866f);
    p = __fmaf_rn(p, f, 0.24022650700f);
    p = __fmaf_rn(p, f, 0.69314718056f);
    p = __fmaf_rn(p, f, 1.0f);
    return __int_as_float(__float_as_int(p) + ((ni - 0x4B400000) << 23));
}
__device__ __forceinline__ float fsigmoid(float xv) {
    float t = fminf(fmaxf(-1.44269504089f * xv, -30.0f), 30.0f);
    float d = 1.0f + fast_exp2s(t);
    float y = __int_as_float(0x7EF477D5 - __float_as_int(d));
    y = y * __fmaf_rn(-d, y, 2.0f);
    y = y * __fmaf_rn(-d, y, 2.0f);
    y = y * __fmaf_rn(-d, y, 2.0f);
    return y;
}

// ---------------- prep: transpose W_hh, fuse biases ----------------
__global__ void prep_kernel(const float* __restrict__ Whh,
                            const float* __restrict__ bih,
                            const float* __restrict__ bhh) {
    int idx = blockIdx.x * blockDim.x + threadIdx.x;
    if (idx < HH * G4) {
        int k = idx >> 9;
        int j = idx & 511;
        g_Wt[idx] = Whh[j * HH + k];
    }
    if (idx < G4) g_b[idx] = bih[idx] + bhh[idx];
}

// ---------------- persistent LSTM kernel (f32x2 packed) ----------------
// CTA: 32 batch rows.  Thread (ty, hx): ty -> 8 rows, hx -> hidden col pair (2hx, 2hx+1).
__global__ void __launch_bounds__(THR, 1) lstm_main(
    const float* __restrict__ x, const float* __restrict__ Wih)
{
    __shared__ ull  hs2[ROWS][HH];   // h duplicated pairs {h,h}  (32 KB)
    __shared__ ull  ws2[INF][4][64]; // packed W_ih pairs          (6 KB)
    __shared__ float xs[ROWS][INF];

    const int tid = threadIdx.x;
    const int hx  = tid & 63;
    const int ty  = tid >> 6;
    const int hc0 = hx * 2;
    const int r0  = ty * 8;
    const int b0  = blockIdx.x * ROWS;

    // zero h (duplicated form)
    for (int i = tid; i < ROWS * HH; i += THR) ((ull*)hs2)[i] = 0ULL;

    // pack W_ih pairs into smem: ws2[kx][g][hx] = {Wih[(g*128+2hx)*3+kx], Wih[(g*128+2hx+1)*3+kx]}
    for (int i = tid; i < INF * 4 * 64; i += THR) {
        int hxx = i & 63, gg = (i >> 6) & 3, kx = i >> 8;
        int j0 = gg * HH + hxx * 2;
        ws2[kx][gg][hxx] = pk(Wih[j0 * INF + kx], Wih[(j0 + 1) * INF + kx]);
    }

    // packed bias pairs
    ull bias2[4];
#pragma unroll
    for (int g = 0; g < 4; ++g)
        bias2[g] = *(const ull*)&g_b[g * HH + hc0];

    const int xr = tid / 3;
    const int xk = tid - xr * 3;
    if (tid < 96) xs[xr][xk] = x[(b0 + xr) * (TT * INF) + xk];  // t = 0
    __syncthreads();

    const ull* __restrict__ Wp = (const ull*)g_Wt;

    ull cst2[8];
#pragma unroll
    for (int r = 0; r < 8; ++r) cst2[r] = 0ULL;

    for (int t = 0; t < TT; ++t) {
        ull z2[4][8];
#pragma unroll
        for (int g = 0; g < 4; ++g)
#pragma unroll
            for (int r = 0; r < 8; ++r) z2[g][r] = bias2[g];

        // x contribution
#pragma unroll
        for (int kx = 0; kx < INF; ++kx) {
            ull wx[4];
#pragma unroll
            for (int g = 0; g < 4; ++g) wx[g] = ws2[kx][g][hx];
#pragma unroll
            for (int r = 0; r < 8; ++r) {
                ull xd = dup2(xs[r0 + r][kx]);
#pragma unroll
                for (int g = 0; g < 4; ++g) z2[g][r] = f2fma(xd, wx[g], z2[g][r]);
            }
        }

        // h @ W_hh^T  — packed: 2 hidden cols per FMA2
#pragma unroll 2
        for (int k = 0; k < HH; k += 2) {
            ull w0[4], w1[4];
#pragma unroll
            for (int g = 0; g < 4; ++g) {
                w0[g] = Wp[k * 256 + g * 64 + hx];
                w1[g] = Wp[(k + 1) * 256 + g * 64 + hx];
            }
#pragma unroll
            for (int r = 0; r < 8; ++r) {
                ulonglong2 hv = *(const ulonglong2*)&hs2[r0 + r][k];  // {hk,hk},{hk1,hk1}
#pragma unroll
                for (int g = 0; g < 4; ++g) z2[g][r] = f2fma(hv.x, w0[g], z2[g][r]);
#pragma unroll
                for (int g = 0; g < 4; ++g) z2[g][r] = f2fma(hv.y, w1[g], z2[g][r]);
            }
        }

        // nonlinearities + cell update, fully packed
        ull hn2[8];
#pragma unroll
        for (int r = 0; r < 8; ++r) {
            ull i_ = sigmoid2(z2[0][r]);
            ull f_ = sigmoid2(z2[1][r]);
            ull g_ = tanh2   (z2[2][r]);
            ull o_ = sigmoid2(z2[3][r]);
            ull cn = f2fma(f_, cst2[r], f2mul(i_, g_));
            cst2[r] = cn;
            hn2[r]  = f2mul(o_, tanh2(cn));
        }

        __syncthreads();   // all reads of hs2 / xs done
#pragma unroll
        for (int r = 0; r < 8; ++r) {
            float2 h = unpk(hn2[r]);
            ulonglong2 st;
            st.x = dup2(h.x);
            st.y = dup2(h.y);
            *(ulonglong2*)&hs2[r0 + r][hc0] = st;
        }
        if (tid < 96 && t + 1 < TT)
            xs[xr][xk] = x[(b0 + xr) * (TT * INF) + (t + 1) * INF + xk];
        __syncthreads();
    }

    // final h -> global (take .x of each duplicated pair)
    for (int i = tid; i < ROWS * HH; i += THR) {
        float2 hvv = unpk(((ull*)hs2)[i]);
        g_h[b0 * HH + i] = hvv.x;
    }
}

// ---------------- BN stats (two-pass, per feature) ----------------
__global__ void bn_stats(const float* __restrict__ gamma,
                         const float* __restrict__ beta) {
    const int j = blockIdx.x;
    const int tid = threadIdx.x;
    __shared__ float red[256];
    __shared__ float mean_s;

    float s = 0.0f;
    for (int r = tid; r < BB; r += 256) s += g_h[r * HH + j];
    red[tid] = s; __syncthreads();
    for (int o = 128; o > 0; o >>= 1) { if (tid < o) red[tid] += red[tid + o]; __syncthreads(); }
    if (tid == 0) mean_s = red[0] * (1.0f / BB);
    __syncthreads();
    const float m = mean_s;

    float s2 = 0.0f;
    for (int r = tid; r < BB; r += 256) { float d = g_h[r * HH + j] - m; s2 += d * d; }
    red[tid] = s2; __syncthreads();
    for (int o = 128; o > 0; o >>= 1) { if (tid < o) red[tid] += red[tid + o]; __syncthreads(); }
    if (tid == 0) {
        float var  = red[0] * (1.0f / BB);
        float rstd = rsqrtf(var + 1e-5f);
        g_scale[j] = rstd * gamma[j];
        g_shift[j] = beta[j] - m * rstd * gamma[j];
    }
}

// ---------------- BN apply + LeakyReLU + FC + sigmoid ----------------
__global__ void out_kernel(const float* __restrict__ fcw,
                           const float* __restrict__ fcb,
                           float* __restrict__ out) {
    const int lane = threadIdx.x & 31;
    const int warp = threadIdx.x >> 5;
    const int b = blockIdx.x * 4 + warp;
    float acc = 0.0f;
#pragma unroll
    for (int q = 0; q < 4; ++q) {
        int j = lane + q * 32;
        float v = __fmaf_rn(g_h[b * HH + j], g_scale[j], g_shift[j]);
        v = (v >= 0.0f) ? v : 0.01f * v;
        acc = __fmaf_rn(v, fcw[j], acc);
    }
#pragma unroll
    for (int o = 16; o > 0; o >>= 1) acc += __shfl_xor_sync(0xffffffffu, acc, o);
    if (lane == 0) out[b] = fsigmoid(acc + fcb[0]);
}

// ---------------- launch ----------------
extern "C" void kernel_launch(void* const* d_in, const int* in_sizes, int n_in,
                              void* d_out, int out_size) {
    const float* x     = (const float*)d_in[0];
    const float* W_ih  = (const float*)d_in[1];
    const float* W_hh  = (const float*)d_in[2];
    const float* b_ih  = (const float*)d_in[3];
    const float* b_hh  = (const float*)d_in[4];
    const float* gamma = (const float*)d_in[5];
    const float* beta  = (const float*)d_in[6];
    const float* fc_w  = (const float*)d_in[7];
    const float* fc_b  = (const float*)d_in[8];
    float* out = (float*)d_out;

    prep_kernel<<<(HH * G4 + 255) / 256, 256>>>(W_hh, b_ih, b_hh);
    lstm_main<<<CTAS, THR>>>(x, W_ih);
    bn_stats<<<HH, 256>>>(gamma, beta);
    out_kernel<<<BB / 4, 128>>>(fc_w, fc_b, out);
}

// round 7
// speedup vs baseline: 2.8455x; 2.8455x over previous
#include <cuda_runtime.h>
#include <cuda_bf16.h>
#include <cstdint>
typedef uint32_t u32; typedef uint64_t u64;

#define BB 4096
#define TT 512
#define HH 128

// dynamic smem layout (bytes)
// W planes: [128 k][264 bf16] stride 528B (256 scol used)
#define SM_WH   0
#define SM_WL   67584
// A stage: 4 planes [64 rows][136 bf16] stride 272B: buf0(hi,lo), buf1(hi,lo)
#define SM_A    135168
#define APLANE  17408
#define SM_WIHB 204800   // float4[256] {wih0,wih1,wih2,bias}
#define SM_XS   208896   // float[2][192]
#define SMEM_DYN 210944

__device__ __align__(16) float g_h[BB*HH];
__device__ float g_scale[HH], g_shift[HH];

// ---------- helpers ----------
__device__ __forceinline__ u32 smem_u32(const void* p){u32 a;asm("{ .reg .u64 t; cvta.to.shared.u64 t,%1; cvt.u32.u64 %0,t; }":"=r"(a):"l"(p));return a;}
__device__ __forceinline__ u32 ctarank(){u32 r;asm("mov.u32 %0,%%cluster_ctarank;":"=r"(r));return r;}
__device__ __forceinline__ u32 mapa_peer(u32 a,u32 pr){u32 r;asm("mapa.shared::cluster.u32 %0,%1,%2;":"=r"(r):"r"(a),"r"(pr));return r;}
__device__ __forceinline__ void st_cluster_u32(u32 a,u32 v){asm volatile("st.shared::cluster.u32 [%0],%1;"::"r"(a),"r"(v):"memory");}
__device__ __forceinline__ float ex2a(float x){float y;asm("ex2.approx.f32 %0,%1;":"=f"(y):"f"(x));return y;}
__device__ __forceinline__ float rcpa(float x){float y;asm("rcp.approx.f32 %0,%1;":"=f"(y):"f"(x));return y;}
__device__ __forceinline__ float sigm(float x){return rcpa(1.0f+ex2a(-1.44269504f*x));}
__device__ __forceinline__ float tanha(float x){return fmaf(-2.0f,rcpa(1.0f+ex2a(2.88539008f*x)),1.0f);}
#define CLUSTER_SYNC() do{asm volatile("barrier.cluster.arrive.aligned;":::"memory");asm volatile("barrier.cluster.wait.aligned;":::"memory");}while(0)

#define LDSM4(r,ad) asm volatile("ldmatrix.sync.aligned.m8n8.x4.shared.b16 {%0,%1,%2,%3},[%4];" \
  : "=r"((r)[0]),"=r"((r)[1]),"=r"((r)[2]),"=r"((r)[3]) : "r"(ad))
#define LDSM2T(r,ad) asm volatile("ldmatrix.sync.aligned.m8n8.x2.trans.shared.b16 {%0,%1},[%2];" \
  : "=r"((r)[0]),"=r"((r)[1]) : "r"(ad))
#define MMA(d,a,b) asm volatile("mma.sync.aligned.m16n8k16.row.col.f32.bf16.bf16.f32 " \
  "{%0,%1,%2,%3},{%4,%5,%6,%7},{%8,%9},{%0,%1,%2,%3};" \
  : "+f"((d)[0]),"+f"((d)[1]),"+f"((d)[2]),"+f"((d)[3]) \
  : "r"((a)[0]),"r"((a)[1]),"r"((a)[2]),"r"((a)[3]),"r"((b)[0]),"r"((b)[1]))

// ---------- persistent mma.sync LSTM ----------
// cluster of 2 CTAs = 64 batch rows; CTA computes 256 gate cols (its 64 j x 4 gates)
// warp w: n = scol [w*32, w*32+32), scol = w*32 + g*8 + jl; M = 64 rows (4 m-tiles)
__global__ void __launch_bounds__(256,1) __cluster_dims__(2,1,1)
lstm_main(const float* __restrict__ x, const float* __restrict__ Wih,
          const float* __restrict__ Whh,
          const float* __restrict__ bih, const float* __restrict__ bhh)
{
    extern __shared__ char smem[];
    const u32 smb = smem_u32(smem);
    const int tid = threadIdx.x, w = tid>>5, lane = tid&31;
    const u32 rank = ctarank();
    const int b0 = (blockIdx.x>>1)*64;

    // ---- init: W split-bf16 -> smem [k][scol] ----
    for (int i = tid; i < 256*128; i += 256) {
        int scol = i >> 7, k = i & 127;
        int g = (scol>>3)&3, ww = scol>>5, jl = scol&7;
        int gcol = g*HH + (int)rank*64 + ww*8 + jl;
        float wv = Whh[gcol*HH + k];
        __nv_bfloat16 hi = __float2bfloat16(wv);
        __nv_bfloat16 lo = __float2bfloat16(wv - __bfloat162float(hi));
        *(__nv_bfloat16*)(smem + SM_WH + k*528 + scol*2) = hi;
        *(__nv_bfloat16*)(smem + SM_WL + k*528 + scol*2) = lo;
    }
    {   int scol = tid, g=(scol>>3)&3, ww=scol>>5, jl=scol&7;
        int gcol = g*HH + (int)rank*64 + ww*8 + jl;
        float4 v = make_float4(Wih[gcol*3], Wih[gcol*3+1], Wih[gcol*3+2],
                               bih[gcol]+bhh[gcol]);
        ((float4*)(smem+SM_WIHB))[scol] = v;
    }
    for (int i = tid; i < 2*APLANE/4; i += 256) ((u32*)(smem+SM_A))[i] = 0;  // zero buf0
    __syncthreads();
    CLUSTER_SYNC();

    // per-thread ldmatrix address components
    const int q = lane>>3, rr = lane&7;
    const u32 rowA_off = (u32)(((q&1)*8+rr)*272 + (q>>1)*16);
    const int Lb = lane & 15;
    const u32 bB_off = (u32)(Lb*528 + w*64);
    const u32 pA = mapa_peer(smb + SM_A, rank^1);
    const int gp = lane>>2, tig = lane&3;

    float creg[16];
#pragma unroll
    for (int i=0;i<16;++i) creg[i]=0.0f;

    for (int t=0; t<TT; ++t) {
        const u32 AH = smb + SM_A + (u32)(t&1)*(2*APLANE);
        const u32 AL = AH + APLANE;
        float xr0=0,xr1=0,xr2=0;
        if (tid < 64) {
            const float* xp = x + (u64)(b0+tid)*(TT*3) + (u64)t*3;
            xr0=xp[0]; xr1=xp[1]; xr2=xp[2];
        }
        float acc[4][4][4];
#pragma unroll
        for (int m=0;m<4;++m)
#pragma unroll
        for (int g=0;g<4;++g)
#pragma unroll
        for (int r2=0;r2<4;++r2) acc[m][g][r2]=0.0f;

#pragma unroll 1
        for (int kt=0; kt<8; ++kt) {
            u32 ah[4][4], al[4][4], bh[4][2], bl[4][2];
            u32 aad = AH + (u32)kt*32 + rowA_off;
            u32 lad = AL + (u32)kt*32 + rowA_off;
#pragma unroll
            for (int m=0;m<4;++m) { LDSM4(ah[m], aad + m*4352); LDSM4(al[m], lad + m*4352); }
            u32 bad = smb + SM_WH + (u32)kt*8448 + bB_off;
            u32 bld = smb + SM_WL + (u32)kt*8448 + bB_off;
#pragma unroll
            for (int g=0;g<4;++g) { LDSM2T(bh[g], bad + g*16); LDSM2T(bl[g], bld + g*16); }
#pragma unroll
            for (int m=0;m<4;++m)
#pragma unroll
            for (int g=0;g<4;++g) {
                MMA(acc[m][g], ah[m], bh[g]);
                MMA(acc[m][g], al[m], bh[g]);
                MMA(acc[m][g], ah[m], bl[g]);
            }
        }
        if (tid < 64) {
            float* xd = (float*)(smem+SM_XS) + (t&1)*192 + tid*3;
            xd[0]=xr0; xd[1]=xr1; xd[2]=xr2;
        }
        __syncthreads();

        // ---- epilogue ----
        const u32 lbuf = (u32)SM_A + (u32)((t+1)&1)*(2*APLANE);
        const u32 pbuf = pA + (u32)((t+1)&1)*(2*APLANE);
        const float4* wb = (const float4*)(smem+SM_WIHB) + w*32;
        float4 wf[4][2];
#pragma unroll
        for (int g=0;g<4;++g){ wf[g][0]=wb[g*8+tig*2]; wf[g][1]=wb[g*8+tig*2+1]; }
        const float* xsb = (const float*)(smem+SM_XS) + (t&1)*192;
        const bool last = (t==TT-1);
#pragma unroll
        for (int m=0;m<4;++m)
#pragma unroll
        for (int rh=0;rh<2;++rh) {
            int rloc = m*16 + gp + rh*8;
            float x0=xsb[rloc*3], x1=xsb[rloc*3+1], x2=xsb[rloc*3+2];
            float hv[2];
#pragma unroll
            for (int p=0;p<2;++p) {
                int di = rh*2+p;
                float zi = acc[m][0][di] + wf[0][p].w; zi=fmaf(x0,wf[0][p].x,fmaf(x1,wf[0][p].y,fmaf(x2,wf[0][p].z,zi)));
                float zf = acc[m][1][di] + wf[1][p].w; zf=fmaf(x0,wf[1][p].x,fmaf(x1,wf[1][p].y,fmaf(x2,wf[1][p].z,zf)));
                float zg = acc[m][2][di] + wf[2][p].w; zg=fmaf(x0,wf[2][p].x,fmaf(x1,wf[2][p].y,fmaf(x2,wf[2][p].z,zg)));
                float zo = acc[m][3][di] + wf[3][p].w; zo=fmaf(x0,wf[3][p].x,fmaf(x1,wf[3][p].y,fmaf(x2,wf[3][p].z,zo)));
                float iv=sigm(zi), fv=sigm(zf), gv=tanha(zg), ov=sigm(zo);
                int ci=(m*2+rh)*2+p;
                float cn=fmaf(fv,creg[ci],iv*gv); creg[ci]=cn;
                hv[p]=ov*tanha(cn);
            }
            int jbase = (int)rank*64 + w*8 + tig*2;
            if (last) {
                *(float2*)&g_h[(u64)(b0+rloc)*HH + jbase] = make_float2(hv[0],hv[1]);
            } else {
                __nv_bfloat16 h0=__float2bfloat16(hv[0]), h1=__float2bfloat16(hv[1]);
                __nv_bfloat16 l0=__float2bfloat16(hv[0]-__bfloat162float(h0));
                __nv_bfloat16 l1=__float2bfloat16(hv[1]-__bfloat162float(h1));
                u32 hp=(u32)__bfloat16_as_ushort(h0)|((u32)__bfloat16_as_ushort(h1)<<16);
                u32 lp=(u32)__bfloat16_as_ushort(l0)|((u32)__bfloat16_as_ushort(l1)<<16);
                u32 off=(u32)(rloc*272 + jbase*2);
                *(u32*)(smem + lbuf + off)          = hp;
                *(u32*)(smem + lbuf + APLANE + off) = lp;
                st_cluster_u32(pbuf + off, hp);
                st_cluster_u32(pbuf + APLANE + off, lp);
            }
        }
        CLUSTER_SYNC();
    }
}

// ---------- BN stats ----------
__global__ void bn_stats(const float* __restrict__ gamma, const float* __restrict__ beta){
    const int j=blockIdx.x, tid=threadIdx.x;
    __shared__ float red[256]; __shared__ float mean_s;
    float s=0.0f;
    for(int r=tid;r<BB;r+=256) s+=g_h[r*HH+j];
    red[tid]=s; __syncthreads();
    for(int o=128;o>0;o>>=1){ if(tid<o) red[tid]+=red[tid+o]; __syncthreads(); }
    if(tid==0) mean_s=red[0]*(1.0f/BB);
    __syncthreads();
    const float m=mean_s;
    float s2=0.0f;
    for(int r=tid;r<BB;r+=256){ float d=g_h[r*HH+j]-m; s2+=d*d; }
    red[tid]=s2; __syncthreads();
    for(int o=128;o>0;o>>=1){ if(tid<o) red[tid]+=red[tid+o]; __syncthreads(); }
    if(tid==0){ float var=red[0]*(1.0f/BB); float rstd=rsqrtf(var+1e-5f);
        g_scale[j]=rstd*gamma[j]; g_shift[j]=beta[j]-m*rstd*gamma[j]; }
}

// ---------- BN apply + LeakyReLU + FC + sigmoid ----------
__global__ void out_kernel(const float* __restrict__ fcw, const float* __restrict__ fcb,
                           float* __restrict__ out){
    const int lanei=threadIdx.x&31, wp=threadIdx.x>>5;
    const int b=blockIdx.x*4+wp;
    float acc=0.0f;
#pragma unroll
    for(int qq=0;qq<4;qq++){
        int j=lanei+qq*32;
        float v=fmaf(g_h[b*HH+j], g_scale[j], g_shift[j]);
        v=(v>=0.0f)?v:0.01f*v;
        acc=fmaf(v, fcw[j], acc);
    }
#pragma unroll
    for(int o=16;o>0;o>>=1) acc+=__shfl_xor_sync(0xffffffffu,acc,o);
    if(lanei==0) out[b]=sigm(acc+fcb[0]);
}

// ---------- launch ----------
extern "C" void kernel_launch(void* const* d_in, const int* in_sizes, int n_in,
                              void* d_out, int out_size){
    const float* x     = (const float*)d_in[0];
    const float* W_ih  = (const float*)d_in[1];
    const float* W_hh  = (const float*)d_in[2];
    const float* b_ih  = (const float*)d_in[3];
    const float* b_hh  = (const float*)d_in[4];
    const float* gamma = (const float*)d_in[5];
    const float* beta  = (const float*)d_in[6];
    const float* fc_w  = (const float*)d_in[7];
    const float* fc_b  = (const float*)d_in[8];
    float* out = (float*)d_out;

    cudaFuncSetAttribute(lstm_main, cudaFuncAttributeMaxDynamicSharedMemorySize, SMEM_DYN);
    lstm_main<<<128, 256, SMEM_DYN>>>(x, W_ih, W_hh, b_ih, b_hh);
    bn_stats<<<HH, 256>>>(gamma, beta);
    out_kernel<<<BB/4, 128>>>(fc_w, fc_b, out);
}

// round 8
// speedup vs baseline: 3.0456x; 1.0703x over previous
#include <cuda_runtime.h>
#include <cuda_bf16.h>
#include <cstdint>
typedef uint32_t u32; typedef uint64_t u64;

#define BB 4096
#define TT 512
#define HH 128

// dynamic smem layout (bytes)
#define SM_WH   0          // W_hi plane: [128 k][264 bf16] stride 528B (256 used)
#define SM_WL   67584      // W_lo plane
#define SM_A    135168     // A stage: buf0(hi,lo), buf1(hi,lo); plane=[64r][136 bf16] stride 272B
#define APLANE  17408
#define SM_WIHB 204800     // float4[256] {wih0,wih1,wih2,bias}
#define SM_XS   208896     // float[192]
#define SMEM_DYN 210944

__device__ __align__(16) float g_h[BB*HH];
__device__ float g_scale[HH], g_shift[HH];

// ---------- helpers ----------
__device__ __forceinline__ u32 smem_u32(const void* p){u32 a;asm("{ .reg .u64 t; cvta.to.shared.u64 t,%1; cvt.u32.u64 %0,t; }":"=r"(a):"l"(p));return a;}
__device__ __forceinline__ u32 ctarank(){u32 r;asm("mov.u32 %0,%%cluster_ctarank;":"=r"(r));return r;}
__device__ __forceinline__ u32 mapa_peer(u32 a,u32 pr){u32 r;asm("mapa.shared::cluster.u32 %0,%1,%2;":"=r"(r):"r"(a),"r"(pr));return r;}
__device__ __forceinline__ void st_cluster_u32(u32 a,u32 v){asm volatile("st.shared::cluster.u32 [%0],%1;"::"r"(a),"r"(v):"memory");}
__device__ __forceinline__ float ex2a(float x){float y;asm("ex2.approx.f32 %0,%1;":"=f"(y):"f"(x));return y;}
__device__ __forceinline__ float rcpa(float x){float y;asm("rcp.approx.f32 %0,%1;":"=f"(y):"f"(x));return y;}
__device__ __forceinline__ float sigm(float x){return rcpa(1.0f+ex2a(-1.44269504f*x));}
__device__ __forceinline__ float tanha(float x){return fmaf(-2.0f,rcpa(1.0f+ex2a(2.88539008f*x)),1.0f);}
#define CLUSTER_SYNC() do{asm volatile("barrier.cluster.arrive.aligned;":::"memory");asm volatile("barrier.cluster.wait.aligned;":::"memory");}while(0)

#define LDSM4(r,ad) asm volatile("ldmatrix.sync.aligned.m8n8.x4.shared.b16 {%0,%1,%2,%3},[%4];" \
  : "=r"((r)[0]),"=r"((r)[1]),"=r"((r)[2]),"=r"((r)[3]) : "r"(ad))
#define LDSM2T(r,ad) asm volatile("ldmatrix.sync.aligned.m8n8.x2.trans.shared.b16 {%0,%1},[%2];" \
  : "=r"((r)[0]),"=r"((r)[1]) : "r"(ad))
#define MMA(d,a,b) asm volatile("mma.sync.aligned.m16n8k16.row.col.f32.bf16.bf16.f32 " \
  "{%0,%1,%2,%3},{%4,%5,%6,%7},{%8,%9},{%0,%1,%2,%3};" \
  : "+f"((d)[0]),"+f"((d)[1]),"+f"((d)[2]),"+f"((d)[3]) \
  : "r"((a)[0]),"r"((a)[1]),"r"((a)[2]),"r"((a)[3]),"r"((b)[0]),"r"((b)[1]))

// ---------- persistent mma.sync LSTM ----------
// cluster of 2 CTAs = 64 batch rows; CTA computes 256 gate cols (its 64 j x 4 gates)
// warp w: scol in [w*32, w*32+32), scol = w*32 + g*8 + jl
// m-PAIR passes: {m0,m1} then {m2,m3}; epilogue(p) overlaps MMA(p+1) via ILP
__global__ void __launch_bounds__(256,1) __cluster_dims__(2,1,1)
lstm_main(const float* __restrict__ x, const float* __restrict__ Wih,
          const float* __restrict__ Whh,
          const float* __restrict__ bih, const float* __restrict__ bhh)
{
    extern __shared__ char smem[];
    const u32 smb = smem_u32(smem);
    const int tid = threadIdx.x, w = tid>>5, lane = tid&31;
    const u32 rank = ctarank();
    const int b0 = (blockIdx.x>>1)*64;

    // ---- init: W split-bf16 -> smem [k][scol] ----
    for (int i = tid; i < 256*128; i += 256) {
        int scol = i >> 7, k = i & 127;
        int g = (scol>>3)&3, ww = scol>>5, jl = scol&7;
        int gcol = g*HH + (int)rank*64 + ww*8 + jl;
        float wv = Whh[gcol*HH + k];
        __nv_bfloat16 hi = __float2bfloat16(wv);
        __nv_bfloat16 lo = __float2bfloat16(wv - __bfloat162float(hi));
        *(__nv_bfloat16*)(smem + SM_WH + k*528 + scol*2) = hi;
        *(__nv_bfloat16*)(smem + SM_WL + k*528 + scol*2) = lo;
    }
    {   int scol = tid, g=(scol>>3)&3, ww=scol>>5, jl=scol&7;
        int gcol = g*HH + (int)rank*64 + ww*8 + jl;
        float4 v = make_float4(Wih[gcol*3], Wih[gcol*3+1], Wih[gcol*3+2],
                               bih[gcol]+bhh[gcol]);
        ((float4*)(smem+SM_WIHB))[scol] = v;
    }
    for (int i = tid; i < 2*APLANE/4; i += 256) ((u32*)(smem+SM_A))[i] = 0;  // zero buf0
    __syncthreads();
    CLUSTER_SYNC();

    // per-thread ldmatrix address components
    const int q = lane>>3, rr = lane&7;
    const u32 rowA_off = (u32)(((q&1)*8+rr)*272 + (q>>1)*16);
    const int Lb = lane & 15;
    const u32 bB_off = (u32)(Lb*528 + w*64);
    const u32 pA = mapa_peer(smb + SM_A, rank^1);
    const int gp = lane>>2, tig = lane&3;
    const int jbase = (int)rank*64 + w*8 + tig*2;

    // hoisted gate weights (time-invariant)
    float4 wf[4][2];
    {   const float4* wb = (const float4*)(smem+SM_WIHB) + w*32;
#pragma unroll
        for (int g=0;g<4;++g){ wf[g][0]=wb[g*8+tig*2]; wf[g][1]=wb[g*8+tig*2+1]; }
    }

    float creg[16];
#pragma unroll
    for (int i=0;i<16;++i) creg[i]=0.0f;

    // x(0) prefetch into regs
    float xr0=0,xr1=0,xr2=0;
    if (tid < 64) {
        const float* xp = x + (u64)(b0+tid)*(TT*3);
        xr0=xp[0]; xr1=xp[1]; xr2=xp[2];
    }

    for (int t=0; t<TT; ++t) {
        const u32 AH = smb + SM_A + (u32)(t&1)*(2*APLANE);
        const u32 AL = AH + APLANE;
        const u32 lbuf = (u32)SM_A + (u32)((t+1)&1)*(2*APLANE);
        const u32 pbuf = pA + (u32)((t+1)&1)*(2*APLANE);
        const bool last = (t==TT-1);

        if (tid < 64) {  // publish x(t)
            float* xd = (float*)(smem+SM_XS) + tid*3;
            xd[0]=xr0; xd[1]=xr1; xd[2]=xr2;
        }
        __syncthreads();
        if (tid < 64 && t+1 < TT) {  // prefetch x(t+1), consumed next step
            const float* xp = x + (u64)(b0+tid)*(TT*3) + (u64)(t+1)*3;
            xr0=xp[0]; xr1=xp[1]; xr2=xp[2];
        }
        const float* xsb = (const float*)(smem+SM_XS);

#pragma unroll
        for (int mp=0; mp<2; ++mp) {
            // ---- GEMM pass for m = 2mp, 2mp+1 ----
            float acc[2][4][4];
#pragma unroll
            for (int mm=0;mm<2;++mm)
#pragma unroll
            for (int g=0;g<4;++g)
#pragma unroll
            for (int r2=0;r2<4;++r2) acc[mm][g][r2]=0.0f;

#pragma unroll
            for (int kt=0; kt<8; ++kt) {
                u32 ah[2][4], al[2][4], bh[4][2], bl[4][2];
                u32 aad = AH + (u32)kt*32 + rowA_off + (u32)mp*8704;
                u32 lad = AL + (u32)kt*32 + rowA_off + (u32)mp*8704;
#pragma unroll
                for (int mm=0;mm<2;++mm) { LDSM4(ah[mm], aad + mm*4352); LDSM4(al[mm], lad + mm*4352); }
                u32 bad = smb + SM_WH + (u32)kt*8448 + bB_off;
                u32 bld = smb + SM_WL + (u32)kt*8448 + bB_off;
#pragma unroll
                for (int g=0;g<4;++g) { LDSM2T(bh[g], bad + g*16); LDSM2T(bl[g], bld + g*16); }
#pragma unroll
                for (int mm=0;mm<2;++mm)
#pragma unroll
                for (int g=0;g<4;++g) {
                    MMA(acc[mm][g], ah[mm], bh[g]);
                    MMA(acc[mm][g], al[mm], bh[g]);
                    MMA(acc[mm][g], ah[mm], bl[g]);
                }
            }
            // ---- epilogue for this m-pair (overlaps next pass's MMA stream) ----
#pragma unroll
            for (int mm=0;mm<2;++mm)
#pragma unroll
            for (int rh=0;rh<2;++rh) {
                int m = mp*2+mm;
                int rloc = m*16 + gp + rh*8;
                float x0=xsb[rloc*3], x1=xsb[rloc*3+1], x2=xsb[rloc*3+2];
                float hv[2];
#pragma unroll
                for (int p=0;p<2;++p) {
                    int di = rh*2+p;
                    float zi = acc[mm][0][di] + wf[0][p].w; zi=fmaf(x0,wf[0][p].x,fmaf(x1,wf[0][p].y,fmaf(x2,wf[0][p].z,zi)));
                    float zf = acc[mm][1][di] + wf[1][p].w; zf=fmaf(x0,wf[1][p].x,fmaf(x1,wf[1][p].y,fmaf(x2,wf[1][p].z,zf)));
                    float zg = acc[mm][2][di] + wf[2][p].w; zg=fmaf(x0,wf[2][p].x,fmaf(x1,wf[2][p].y,fmaf(x2,wf[2][p].z,zg)));
                    float zo = acc[mm][3][di] + wf[3][p].w; zo=fmaf(x0,wf[3][p].x,fmaf(x1,wf[3][p].y,fmaf(x2,wf[3][p].z,zo)));
                    float iv=sigm(zi), fv=sigm(zf), gv=tanha(zg), ov=sigm(zo);
                    int ci=(m*2+rh)*2+p;
                    float cn=fmaf(fv,creg[ci],iv*gv); creg[ci]=cn;
                    hv[p]=ov*tanha(cn);
                }
                if (last) {
                    *(float2*)&g_h[(u64)(b0+rloc)*HH + jbase] = make_float2(hv[0],hv[1]);
                } else {
                    __nv_bfloat16 h0=__float2bfloat16(hv[0]), h1=__float2bfloat16(hv[1]);
                    __nv_bfloat16 l0=__float2bfloat16(hv[0]-__bfloat162float(h0));
                    __nv_bfloat16 l1=__float2bfloat16(hv[1]-__bfloat162float(h1));
                    u32 hp=(u32)__bfloat16_as_ushort(h0)|((u32)__bfloat16_as_ushort(h1)<<16);
                    u32 lp=(u32)__bfloat16_as_ushort(l0)|((u32)__bfloat16_as_ushort(l1)<<16);
                    u32 off=(u32)(rloc*272 + jbase*2);
                    *(u32*)(smem + lbuf + off)          = hp;
                    *(u32*)(smem + lbuf + APLANE + off) = lp;
                    st_cluster_u32(pbuf + off, hp);
                    st_cluster_u32(pbuf + APLANE + off, lp);
                }
            }
        }
        CLUSTER_SYNC();
    }
}

// ---------- BN stats ----------
__global__ void bn_stats(const float* __restrict__ gamma, const float* __restrict__ beta){
    const int j=blockIdx.x, tid=threadIdx.x;
    __shared__ float red[256]; __shared__ float mean_s;
    float s=0.0f;
    for(int r=tid;r<BB;r+=256) s+=g_h[r*HH+j];
    red[tid]=s; __syncthreads();
    for(int o=128;o>0;o>>=1){ if(tid<o) red[tid]+=red[tid+o]; __syncthreads(); }
    if(tid==0) mean_s=red[0]*(1.0f/BB);
    __syncthreads();
    const float m=mean_s;
    float s2=0.0f;
    for(int r=tid;r<BB;r+=256){ float d=g_h[r*HH+j]-m; s2+=d*d; }
    red[tid]=s2; __syncthreads();
    for(int o=128;o>0;o>>=1){ if(tid<o) red[tid]+=red[tid+o]; __syncthreads(); }
    if(tid==0){ float var=red[0]*(1.0f/BB); float rstd=rsqrtf(var+1e-5f);
        g_scale[j]=rstd*gamma[j]; g_shift[j]=beta[j]-m*rstd*gamma[j]; }
}

// ---------- BN apply + LeakyReLU + FC + sigmoid ----------
__global__ void out_kernel(const float* __restrict__ fcw, const float* __restrict__ fcb,
                           float* __restrict__ out){
    const int lanei=threadIdx.x&31, wp=threadIdx.x>>5;
    const int b=blockIdx.x*4+wp;
    float acc=0.0f;
#pragma unroll
    for(int qq=0;qq<4;qq++){
        int j=lanei+qq*32;
        float v=fmaf(g_h[b*HH+j], g_scale[j], g_shift[j]);
        v=(v>=0.0f)?v:0.01f*v;
        acc=fmaf(v, fcw[j], acc);
    }
#pragma unroll
    for(int o=16;o>0;o>>=1) acc+=__shfl_xor_sync(0xffffffffu,acc,o);
    if(lanei==0) out[b]=sigm(acc+fcb[0]);
}

// ---------- launch ----------
extern "C" void kernel_launch(void* const* d_in, const int* in_sizes, int n_in,
                              void* d_out, int out_size){
    const float* x     = (const float*)d_in[0];
    const float* W_ih  = (const float*)d_in[1];
    const float* W_hh  = (const float*)d_in[2];
    const float* b_ih  = (const float*)d_in[3];
    const float* b_hh  = (const float*)d_in[4];
    const float* gamma = (const float*)d_in[5];
    const float* beta  = (const float*)d_in[6];
    const float* fc_w  = (const float*)d_in[7];
    const float* fc_b  = (const float*)d_in[8];
    float* out = (float*)d_out;

    cudaFuncSetAttribute(lstm_main, cudaFuncAttributeMaxDynamicSharedMemorySize, SMEM_DYN);
    lstm_main<<<128, 256, SMEM_DYN>>>(x, W_ih, W_hh, b_ih, b_hh);
    bn_stats<<<HH, 256>>>(gamma, beta);
    out_kernel<<<BB/4, 128>>>(fc_w, fc_b, out);
}

// round 9
// speedup vs baseline: 3.2866x; 1.0791x over previous
#include <cuda_runtime.h>
#include <cuda_bf16.h>
#include <cstdint>
typedef uint32_t u32; typedef uint64_t u64;

#define BB 4096
#define TT 512
#define HH 128

// dynamic smem layout (bytes)
#define SM_WH   0          // W_hi plane: [128 k][264 bf16] stride 528B (256 used)
#define SM_WL   67584      // W_lo plane
#define SM_A    135168     // A stage: buf0(hi,lo), buf1(hi,lo); plane=[64r][136 bf16] stride 272B
#define APLANE  17408
#define SM_WIHB 204800     // float4[256] {wih0,wih1,wih2,bias}
#define SM_XS   208896     // float[192]
#define SMEM_DYN 210944

__device__ __align__(16) float g_h[BB*HH];
__device__ float g_scale[HH], g_shift[HH];

// ---------- helpers ----------
__device__ __forceinline__ u32 smem_u32(const void* p){u32 a;asm("{ .reg .u64 t; cvta.to.shared.u64 t,%1; cvt.u32.u64 %0,t; }":"=r"(a):"l"(p));return a;}
__device__ __forceinline__ u32 ctarank(){u32 r;asm("mov.u32 %0,%%cluster_ctarank;":"=r"(r));return r;}
__device__ __forceinline__ u32 mapa_peer(u32 a,u32 pr){u32 r;asm("mapa.shared::cluster.u32 %0,%1,%2;":"=r"(r):"r"(a),"r"(pr));return r;}
__device__ __forceinline__ void st_cluster_u32(u32 a,u32 v){asm volatile("st.shared::cluster.u32 [%0],%1;"::"r"(a),"r"(v):"memory");}
__device__ __forceinline__ float ex2a(float x){float y;asm("ex2.approx.f32 %0,%1;":"=f"(y):"f"(x));return y;}
__device__ __forceinline__ float rcpa(float x){float y;asm("rcp.approx.f32 %0,%1;":"=f"(y):"f"(x));return y;}
__device__ __forceinline__ float sigm(float x){return rcpa(1.0f+ex2a(-1.44269504f*x));}
__device__ __forceinline__ float tanha(float x){return fmaf(-2.0f,rcpa(1.0f+ex2a(2.88539008f*x)),1.0f);}
#define CLUSTER_SYNC() do{asm volatile("barrier.cluster.arrive.aligned;":::"memory");asm volatile("barrier.cluster.wait.aligned;":::"memory");}while(0)

#define LDSM4(r,ad) asm volatile("ldmatrix.sync.aligned.m8n8.x4.shared.b16 {%0,%1,%2,%3},[%4];" \
  : "=r"((r)[0]),"=r"((r)[1]),"=r"((r)[2]),"=r"((r)[3]) : "r"(ad))
#define LDSM2T(r,ad) asm volatile("ldmatrix.sync.aligned.m8n8.x2.trans.shared.b16 {%0,%1},[%2];" \
  : "=r"((r)[0]),"=r"((r)[1]) : "r"(ad))
#define MMA(d,a,b) asm volatile("mma.sync.aligned.m16n8k16.row.col.f32.bf16.bf16.f32 " \
  "{%0,%1,%2,%3},{%4,%5,%6,%7},{%8,%9},{%0,%1,%2,%3};" \
  : "+f"((d)[0]),"+f"((d)[1]),"+f"((d)[2]),"+f"((d)[3]) \
  : "r"((a)[0]),"r"((a)[1]),"r"((a)[2]),"r"((a)[3]),"r"((b)[0]),"r"((b)[1]))

// ---------- persistent mma.sync LSTM ----------
// cluster of 2 CTAs = 64 batch rows; CTA computes 256 gate cols (its 64 j x 4 gates)
// 512 threads / 16 warps: warp w -> (mhalf = w>>3 : rows 32*mhalf..+32, wn = w&7 : scol strip)
// scol = wn*32 + g*8 + jl
__global__ void __launch_bounds__(512,1) __cluster_dims__(2,1,1)
lstm_main(const float* __restrict__ x, const float* __restrict__ Wih,
          const float* __restrict__ Whh,
          const float* __restrict__ bih, const float* __restrict__ bhh)
{
    extern __shared__ char smem[];
    const u32 smb = smem_u32(smem);
    const int tid = threadIdx.x, w = tid>>5, lane = tid&31;
    const int wn = w&7, mhalf = w>>3;
    const u32 rank = ctarank();
    const int b0 = (blockIdx.x>>1)*64;

    // ---- init: W split-bf16 -> smem [k][scol] ----
    for (int i = tid; i < 256*128; i += 512) {
        int scol = i >> 7, k = i & 127;
        int g = (scol>>3)&3, ww = scol>>5, jl = scol&7;
        int gcol = g*HH + (int)rank*64 + ww*8 + jl;
        float wv = Whh[gcol*HH + k];
        __nv_bfloat16 hi = __float2bfloat16(wv);
        __nv_bfloat16 lo = __float2bfloat16(wv - __bfloat162float(hi));
        *(__nv_bfloat16*)(smem + SM_WH + k*528 + scol*2) = hi;
        *(__nv_bfloat16*)(smem + SM_WL + k*528 + scol*2) = lo;
    }
    if (tid < 256) {
        int scol = tid, g=(scol>>3)&3, ww=scol>>5, jl=scol&7;
        int gcol = g*HH + (int)rank*64 + ww*8 + jl;
        float4 v = make_float4(Wih[gcol*3], Wih[gcol*3+1], Wih[gcol*3+2],
                               bih[gcol]+bhh[gcol]);
        ((float4*)(smem+SM_WIHB))[scol] = v;
    }
    for (int i = tid; i < 2*APLANE/4; i += 512) ((u32*)(smem+SM_A))[i] = 0;  // zero buf0
    __syncthreads();
    CLUSTER_SYNC();

    // per-thread ldmatrix address components
    const int q = lane>>3, rr = lane&7;
    const u32 rowA_off = (u32)(((q&1)*8+rr)*272 + (q>>1)*16) + (u32)mhalf*8704;
    const int Lb = lane & 15;
    const u32 bB_off = (u32)(Lb*528 + wn*64);
    const u32 pA = mapa_peer(smb + SM_A, rank^1);
    const int gp = lane>>2, tig = lane&3;
    const int jbase = (int)rank*64 + wn*8 + tig*2;

    // hoisted gate weights (time-invariant)
    float4 wf[4][2];
    {   const float4* wb = (const float4*)(smem+SM_WIHB) + wn*32;
#pragma unroll
        for (int g=0;g<4;++g){ wf[g][0]=wb[g*8+tig*2]; wf[g][1]=wb[g*8+tig*2+1]; }
    }

    float creg[8];
#pragma unroll
    for (int i=0;i<8;++i) creg[i]=0.0f;

    // x(0) prefetch into regs
    float xr0=0,xr1=0,xr2=0;
    if (tid < 64) {
        const float* xp = x + (u64)(b0+tid)*(TT*3);
        xr0=xp[0]; xr1=xp[1]; xr2=xp[2];
    }

    for (int t=0; t<TT; ++t) {
        const u32 AH = smb + SM_A + (u32)(t&1)*(2*APLANE);
        const u32 AL = AH + APLANE;
        const u32 lbuf = (u32)SM_A + (u32)((t+1)&1)*(2*APLANE);
        const u32 pbuf = pA + (u32)((t+1)&1)*(2*APLANE);
        const bool last = (t==TT-1);

        if (tid < 64) {  // publish x(t)
            float* xd = (float*)(smem+SM_XS) + tid*3;
            xd[0]=xr0; xd[1]=xr1; xd[2]=xr2;
        }
        __syncthreads();
        if (tid < 64 && t+1 < TT) {  // prefetch x(t+1), consumed next step
            const float* xp = x + (u64)(b0+tid)*(TT*3) + (u64)(t+1)*3;
            xr0=xp[0]; xr1=xp[1]; xr2=xp[2];
        }
        const float* xsb = (const float*)(smem+SM_XS);

        // ---- GEMM: this warp's 2 m-tiles x 32 gate cols, K=128, 3 split terms ----
        float acc[2][4][4];
#pragma unroll
        for (int mm=0;mm<2;++mm)
#pragma unroll
        for (int g=0;g<4;++g)
#pragma unroll
        for (int r2=0;r2<4;++r2) acc[mm][g][r2]=0.0f;

#pragma unroll
        for (int kt=0; kt<8; ++kt) {
            u32 ah[2][4], al[2][4], bh[4][2], bl[4][2];
            u32 aad = AH + (u32)kt*32 + rowA_off;
            u32 lad = AL + (u32)kt*32 + rowA_off;
#pragma unroll
            for (int mm=0;mm<2;++mm) { LDSM4(ah[mm], aad + mm*4352); LDSM4(al[mm], lad + mm*4352); }
            u32 bad = smb + SM_WH + (u32)kt*8448 + bB_off;
            u32 bld = smb + SM_WL + (u32)kt*8448 + bB_off;
#pragma unroll
            for (int g=0;g<4;++g) { LDSM2T(bh[g], bad + g*16); LDSM2T(bl[g], bld + g*16); }
#pragma unroll
            for (int mm=0;mm<2;++mm)
#pragma unroll
            for (int g=0;g<4;++g) {
                MMA(acc[mm][g], ah[mm], bh[g]);
                MMA(acc[mm][g], al[mm], bh[g]);
                MMA(acc[mm][g], ah[mm], bl[g]);
            }
        }

        // ---- epilogue (this warp's 32 rows) ----
#pragma unroll
        for (int mm=0;mm<2;++mm)
#pragma unroll
        for (int rh=0;rh<2;++rh) {
            int m = mhalf*2+mm;
            int rloc = m*16 + gp + rh*8;
            float x0=xsb[rloc*3], x1=xsb[rloc*3+1], x2=xsb[rloc*3+2];
            float hv[2];
#pragma unroll
            for (int p=0;p<2;++p) {
                int di = rh*2+p;
                float zi = acc[mm][0][di] + wf[0][p].w; zi=fmaf(x0,wf[0][p].x,fmaf(x1,wf[0][p].y,fmaf(x2,wf[0][p].z,zi)));
                float zf = acc[mm][1][di] + wf[1][p].w; zf=fmaf(x0,wf[1][p].x,fmaf(x1,wf[1][p].y,fmaf(x2,wf[1][p].z,zf)));
                float zg = acc[mm][2][di] + wf[2][p].w; zg=fmaf(x0,wf[2][p].x,fmaf(x1,wf[2][p].y,fmaf(x2,wf[2][p].z,zg)));
                float zo = acc[mm][3][di] + wf[3][p].w; zo=fmaf(x0,wf[3][p].x,fmaf(x1,wf[3][p].y,fmaf(x2,wf[3][p].z,zo)));
                float iv=sigm(zi), fv=sigm(zf), gv=tanha(zg), ov=sigm(zo);
                int ci=(mm*2+rh)*2+p;
                float cn=fmaf(fv,creg[ci],iv*gv); creg[ci]=cn;
                hv[p]=ov*tanha(cn);
            }
            if (last) {
                *(float2*)&g_h[(u64)(b0+rloc)*HH + jbase] = make_float2(hv[0],hv[1]);
            } else {
                __nv_bfloat16 h0=__float2bfloat16(hv[0]), h1=__float2bfloat16(hv[1]);
                __nv_bfloat16 l0=__float2bfloat16(hv[0]-__bfloat162float(h0));
                __nv_bfloat16 l1=__float2bfloat16(hv[1]-__bfloat162float(h1));
                u32 hp=(u32)__bfloat16_as_ushort(h0)|((u32)__bfloat16_as_ushort(h1)<<16);
                u32 lp=(u32)__bfloat16_as_ushort(l0)|((u32)__bfloat16_as_ushort(l1)<<16);
                u32 off=(u32)(rloc*272 + jbase*2);
                *(u32*)(smem + lbuf + off)          = hp;
                *(u32*)(smem + lbuf + APLANE + off) = lp;
                st_cluster_u32(pbuf + off, hp);
                st_cluster_u32(pbuf + APLANE + off, lp);
            }
        }
        CLUSTER_SYNC();
    }
}

// ---------- BN stats ----------
__global__ void bn_stats(const float* __restrict__ gamma, const float* __restrict__ beta){
    const int j=blockIdx.x, tid=threadIdx.x;
    __shared__ float red[256]; __shared__ float mean_s;
    float s=0.0f;
    for(int r=tid;r<BB;r+=256) s+=g_h[r*HH+j];
    red[tid]=s; __syncthreads();
    for(int o=128;o>0;o>>=1){ if(tid<o) red[tid]+=red[tid+o]; __syncthreads(); }
    if(tid==0) mean_s=red[0]*(1.0f/BB);
    __syncthreads();
    const float m=mean_s;
    float s2=0.0f;
    for(int r=tid;r<BB;r+=256){ float d=g_h[r*HH+j]-m; s2+=d*d; }
    red[tid]=s2; __syncthreads();
    for(int o=128;o>0;o>>=1){ if(tid<o) red[tid]+=red[tid+o]; __syncthreads(); }
    if(tid==0){ float var=red[0]*(1.0f/BB); float rstd=rsqrtf(var+1e-5f);
        g_scale[j]=rstd*gamma[j]; g_shift[j]=beta[j]-m*rstd*gamma[j]; }
}

// ---------- BN apply + LeakyReLU + FC + sigmoid ----------
__global__ void out_kernel(const float* __restrict__ fcw, const float* __restrict__ fcb,
                           float* __restrict__ out){
    const int lanei=threadIdx.x&31, wp=threadIdx.x>>5;
    const int b=blockIdx.x*4+wp;
    float acc=0.0f;
#pragma unroll
    for(int qq=0;qq<4;qq++){
        int j=lanei+qq*32;
        float v=fmaf(g_h[b*HH+j], g_scale[j], g_shift[j]);
        v=(v>=0.0f)?v:0.01f*v;
        acc=fmaf(v, fcw[j], acc);
    }
#pragma unroll
    for(int o=16;o>0;o>>=1) acc+=__shfl_xor_sync(0xffffffffu,acc,o);
    if(lanei==0) out[b]=sigm(acc+fcb[0]);
}

// ---------- launch ----------
extern "C" void kernel_launch(void* const* d_in, const int* in_sizes, int n_in,
                              void* d_out, int out_size){
    const float* x     = (const float*)d_in[0];
    const float* W_ih  = (const float*)d_in[1];
    const float* W_hh  = (const float*)d_in[2];
    const float* b_ih  = (const float*)d_in[3];
    const float* b_hh  = (const float*)d_in[4];
    const float* gamma = (const float*)d_in[5];
    const float* beta  = (const float*)d_in[6];
    const float* fc_w  = (const float*)d_in[7];
    const float* fc_b  = (const float*)d_in[8];
    float* out = (float*)d_out;

    cudaFuncSetAttribute(lstm_main, cudaFuncAttributeMaxDynamicSharedMemorySize, SMEM_DYN);
    lstm_main<<<128, 512, SMEM_DYN>>>(x, W_ih, W_hh, b_ih, b_hh);
    bn_stats<<<HH, 256>>>(gamma, beta);
    out_kernel<<<BB/4, 128>>>(fc_w, fc_b, out);
}

// round 10
// speedup vs baseline: 4.2053x; 1.2795x over previous
#include <cuda_runtime.h>
#include <cuda_fp16.h>
#include <cstdint>
typedef uint32_t u32; typedef uint64_t u64;

#define BB 4096
#define TT 512
#define HH 128

// dynamic smem layout (bytes)
// B: W_hi fp16 [144 k-rows][264 cols] stride 528B (rows 0-127 Whh_hi, 128-130 Wih, 131 bias, 132-143 zero)
#define SM_WH 0
// A: 4 planes [64 rows][152 fp16] stride 304B: buf0(hi,lo), buf1(hi,lo)
// cols 0-127 = h (k), cols 128-131 = x-chunk [x0,x1,x2,1 / x_lo,0], 132-151 zero
#define SM_A 76032
#define APLANE 19456
#define SMEM_DYN (76032 + 4*19456)

__device__ __align__(16) float g_h[BB*HH];
__device__ float g_scale[HH], g_shift[HH];

// ---------- helpers ----------
__device__ __forceinline__ u32 smem_u32(const void* p){u32 a;asm("{ .reg .u64 t; cvta.to.shared.u64 t,%1; cvt.u32.u64 %0,t; }":"=r"(a):"l"(p));return a;}
__device__ __forceinline__ u32 ctarank(){u32 r;asm("mov.u32 %0,%%cluster_ctarank;":"=r"(r));return r;}
__device__ __forceinline__ u32 mapa_peer(u32 a,u32 pr){u32 r;asm("mapa.shared::cluster.u32 %0,%1,%2;":"=r"(r):"r"(a),"r"(pr));return r;}
__device__ __forceinline__ void st_cluster_u32(u32 a,u32 v){asm volatile("st.shared::cluster.u32 [%0],%1;"::"r"(a),"r"(v):"memory");}
__device__ __forceinline__ float ex2a(float x){float y;asm("ex2.approx.f32 %0,%1;":"=f"(y):"f"(x));return y;}
__device__ __forceinline__ float rcpa(float x){float y;asm("rcp.approx.f32 %0,%1;":"=f"(y):"f"(x));return y;}
__device__ __forceinline__ float sigm(float x){return rcpa(1.0f+ex2a(-1.44269504f*x));}
__device__ __forceinline__ float tanha(float x){return fmaf(-2.0f,rcpa(1.0f+ex2a(2.88539008f*x)),1.0f);}
__device__ __forceinline__ u32 pkh(__half a,__half b){return (u32)__half_as_ushort(a)|((u32)__half_as_ushort(b)<<16);}
#define CLUSTER_SYNC() do{asm volatile("barrier.cluster.arrive.aligned;":::"memory");asm volatile("barrier.cluster.wait.aligned;":::"memory");}while(0)

#define LDSM4(r,ad) asm volatile("ldmatrix.sync.aligned.m8n8.x4.shared.b16 {%0,%1,%2,%3},[%4];" \
  : "=r"((r)[0]),"=r"((r)[1]),"=r"((r)[2]),"=r"((r)[3]) : "r"(ad))
#define LDSM2T(r,ad) asm volatile("ldmatrix.sync.aligned.m8n8.x2.trans.shared.b16 {%0,%1},[%2];" \
  : "=r"((r)[0]),"=r"((r)[1]) : "r"(ad))
#define MMA(d,a,b) asm volatile("mma.sync.aligned.m16n8k16.row.col.f32.f16.f16.f32 " \
  "{%0,%1,%2,%3},{%4,%5,%6,%7},{%8,%9},{%0,%1,%2,%3};" \
  : "+f"((d)[0]),"+f"((d)[1]),"+f"((d)[2]),"+f"((d)[3]) \
  : "r"((a)[0]),"r"((a)[1]),"r"((a)[2]),"r"((a)[3]),"r"((b)[0]),"r"((b)[1]))

// ---------- persistent mma.sync LSTM (2-term fp16 split, x/bias fused) ----------
// cluster of 2 CTAs = 64 batch rows; CTA computes 256 gate cols (its 64 j x 4 gates)
// 512 threads / 16 warps: warp w -> (mhalf = w>>3 : 32 rows, wn = w&7 : scol strip of 32)
__global__ void __launch_bounds__(512,1) __cluster_dims__(2,1,1)
lstm_main(const float* __restrict__ x, const float* __restrict__ Wih,
          const float* __restrict__ Whh,
          const float* __restrict__ bih, const float* __restrict__ bhh)
{
    extern __shared__ char smem[];
    const u32 smb = smem_u32(smem);
    const int tid = threadIdx.x, w = tid>>5, lane = tid&31;
    const int wn = w&7, mhalf = w>>3;
    const u32 rank = ctarank();
    const int b0 = (blockIdx.x>>1)*64;

    // ---- init B: W_hh hi plane ----
    for (int i = tid; i < 256*128; i += 512) {
        int scol = i >> 7, k = i & 127;
        int g = (scol>>3)&3, ww = scol>>5, jl = scol&7;
        int gcol = g*HH + (int)rank*64 + ww*8 + jl;
        *(__half*)(smem + SM_WH + k*528 + scol*2) = __float2half_rn(Whh[gcol*HH + k]);
    }
    if (tid < 256) {  // x-chunk B rows: wih0..2, bias
        int scol = tid, g=(scol>>3)&3, ww=scol>>5, jl=scol&7;
        int gcol = g*HH + (int)rank*64 + ww*8 + jl;
#pragma unroll
        for (int kk=0;kk<3;++kk)
            *(__half*)(smem + SM_WH + (128+kk)*528 + scol*2) = __float2half_rn(Wih[gcol*3+kk]);
        *(__half*)(smem + SM_WH + 131*528 + scol*2) = __float2half_rn(bih[gcol]+bhh[gcol]);
    }
    for (int i = tid; i < 12*264; i += 512) {  // zero B rows 132..143
        int r2 = i/264, c2 = i%264;
        *(__half*)(smem + SM_WH + (132+r2)*528 + c2*2) = __ushort_as_half((unsigned short)0);
    }
    for (int i = tid; i < 4*APLANE/4; i += 512) ((u32*)(smem+SM_A))[i] = 0;  // zero A
    __syncthreads();
    CLUSTER_SYNC();

    // per-thread ldmatrix address components
    const int q = lane>>3, rr = lane&7;
    const u32 rowA_off = (u32)(((q&1)*8+rr)*304 + (q>>1)*16) + (u32)mhalf*9728;
    const int Lb = lane & 15;
    const u32 bB_off = (u32)(Lb*528 + wn*64);
    const u32 pA = mapa_peer(smb + SM_A, rank^1);
    const int gp = lane>>2, tig = lane&3;
    const int jbase = (int)rank*64 + wn*8 + tig*2;

    float creg[8];
#pragma unroll
    for (int i=0;i<8;++i) creg[i]=0.0f;

    // x(0) prefetch into regs
    float xr0=0,xr1=0,xr2=0;
    if (tid < 64) {
        const float* xp = x + (u64)(b0+tid)*(TT*3);
        xr0=xp[0]; xr1=xp[1]; xr2=xp[2];
    }

    for (int t=0; t<TT; ++t) {
        const u32 AHo = (u32)SM_A + (u32)(t&1)*(2*APLANE);
        const u32 AH  = smb + AHo;
        const u32 AL  = AH + APLANE;
        const u32 lbufo = (u32)SM_A + (u32)((t+1)&1)*(2*APLANE);
        const u32 pbuf  = pA + (u32)((t+1)&1)*(2*APLANE);
        const bool last = (t==TT-1);

        if (tid < 64) {  // publish x(t) into current A x-chunk (hi + lo planes)
            __half h0=__float2half_rn(xr0), h1=__float2half_rn(xr1), h2=__float2half_rn(xr2);
            __half l0=__float2half_rn(xr0-__half2float(h0));
            __half l1=__float2half_rn(xr1-__half2float(h1));
            __half l2=__float2half_rn(xr2-__half2float(h2));
            u32 off = AHo + (u32)tid*304 + 256;
            *(u32*)(smem + off)     = pkh(h0,h1);
            *(u32*)(smem + off + 4) = pkh(h2,__float2half_rn(1.0f));
            *(u32*)(smem + off + APLANE)     = pkh(l0,l1);
            *(u32*)(smem + off + APLANE + 4) = pkh(l2,__ushort_as_half((unsigned short)0));
        }
        __syncthreads();
        if (tid < 64 && t+1 < TT) {  // prefetch x(t+1)
            const float* xp = x + (u64)(b0+tid)*(TT*3) + (u64)(t+1)*3;
            xr0=xp[0]; xr1=xp[1]; xr2=xp[2];
        }

        // ---- GEMM: 2 m-tiles x 32 gate cols, 9 K-chunks (8 h + 1 x), 2 terms ----
        float acc[2][4][4];
#pragma unroll
        for (int mm=0;mm<2;++mm)
#pragma unroll
        for (int g=0;g<4;++g)
#pragma unroll
        for (int r2=0;r2<4;++r2) acc[mm][g][r2]=0.0f;

#pragma unroll
        for (int kt=0; kt<9; ++kt) {
            u32 ah[2][4], al[2][4], bh[4][2];
            u32 aad = AH + (u32)kt*32 + rowA_off;
            u32 lad = AL + (u32)kt*32 + rowA_off;
#pragma unroll
            for (int mm=0;mm<2;++mm) { LDSM4(ah[mm], aad + mm*4864); LDSM4(al[mm], lad + mm*4864); }
            u32 bad = smb + SM_WH + (u32)kt*8448 + bB_off;
#pragma unroll
            for (int g=0;g<4;++g) LDSM2T(bh[g], bad + g*16);
#pragma unroll
            for (int mm=0;mm<2;++mm)
#pragma unroll
            for (int g=0;g<4;++g) {
                MMA(acc[mm][g], ah[mm], bh[g]);
                MMA(acc[mm][g], al[mm], bh[g]);
            }
        }

        // ---- epilogue (this warp's 32 rows): z = acc directly ----
#pragma unroll
        for (int mm=0;mm<2;++mm)
#pragma unroll
        for (int rh=0;rh<2;++rh) {
            int m = mhalf*2+mm;
            int rloc = m*16 + gp + rh*8;
            float hv[2];
#pragma unroll
            for (int p=0;p<2;++p) {
                int di = rh*2+p;
                float iv=sigm(acc[mm][0][di]);
                float fv=sigm(acc[mm][1][di]);
                float gv=tanha(acc[mm][2][di]);
                float ov=sigm(acc[mm][3][di]);
                int ci=(mm*2+rh)*2+p;
                float cn=fmaf(fv,creg[ci],iv*gv); creg[ci]=cn;
                hv[p]=ov*tanha(cn);
            }
            if (last) {
                *(float2*)&g_h[(u64)(b0+rloc)*HH + jbase] = make_float2(hv[0],hv[1]);
            } else {
                __half h0=__float2half_rn(hv[0]), h1=__float2half_rn(hv[1]);
                __half l0=__float2half_rn(hv[0]-__half2float(h0));
                __half l1=__float2half_rn(hv[1]-__half2float(h1));
                u32 hp=pkh(h0,h1), lp=pkh(l0,l1);
                u32 off=(u32)(rloc*304 + jbase*2);
                *(u32*)(smem + lbufo + off)          = hp;
                *(u32*)(smem + lbufo + APLANE + off) = lp;
                st_cluster_u32(pbuf + off, hp);
                st_cluster_u32(pbuf + APLANE + off, lp);
            }
        }
        CLUSTER_SYNC();
    }
}

// ---------- BN stats ----------
__global__ void bn_stats(const float* __restrict__ gamma, const float* __restrict__ beta){
    const int j=blockIdx.x, tid=threadIdx.x;
    __shared__ float red[256]; __shared__ float mean_s;
    float s=0.0f;
    for(int r=tid;r<BB;r+=256) s+=g_h[r*HH+j];
    red[tid]=s; __syncthreads();
    for(int o=128;o>0;o>>=1){ if(tid<o) red[tid]+=red[tid+o]; __syncthreads(); }
    if(tid==0) mean_s=red[0]*(1.0f/BB);
    __syncthreads();
    const float m=mean_s;
    float s2=0.0f;
    for(int r=tid;r<BB;r+=256){ float d=g_h[r*HH+j]-m; s2+=d*d; }
    red[tid]=s2; __syncthreads();
    for(int o=128;o>0;o>>=1){ if(tid<o) red[tid]+=red[tid+o]; __syncthreads(); }
    if(tid==0){ float var=red[0]*(1.0f/BB); float rstd=rsqrtf(var+1e-5f);
        g_scale[j]=rstd*gamma[j]; g_shift[j]=beta[j]-m*rstd*gamma[j]; }
}

// ---------- BN apply + LeakyReLU + FC + sigmoid ----------
__global__ void out_kernel(const float* __restrict__ fcw, const float* __restrict__ fcb,
                           float* __restrict__ out){
    const int lanei=threadIdx.x&31, wp=threadIdx.x>>5;
    const int b=blockIdx.x*4+wp;
    float acc=0.0f;
#pragma unroll
    for(int qq=0;qq<4;qq++){
        int j=lanei+qq*32;
        float v=fmaf(g_h[b*HH+j], g_scale[j], g_shift[j]);
        v=(v>=0.0f)?v:0.01f*v;
        acc=fmaf(v, fcw[j], acc);
    }
#pragma unroll
    for(int o=16;o>0;o>>=1) acc+=__shfl_xor_sync(0xffffffffu,acc,o);
    if(lanei==0) out[b]=sigm(acc+fcb[0]);
}

// ---------- launch ----------
extern "C" void kernel_launch(void* const* d_in, const int* in_sizes, int n_in,
                              void* d_out, int out_size){
    const float* x     = (const float*)d_in[0];
    const float* W_ih  = (const float*)d_in[1];
    const float* W_hh  = (const float*)d_in[2];
    const float* b_ih  = (const float*)d_in[3];
    const float* b_hh  = (const float*)d_in[4];
    const float* gamma = (const float*)d_in[5];
    const float* beta  = (const float*)d_in[6];
    const float* fc_w  = (const float*)d_in[7];
    const float* fc_b  = (const float*)d_in[8];
    float* out = (float*)d_out;

    cudaFuncSetAttribute(lstm_main, cudaFuncAttributeMaxDynamicSharedMemorySize, SMEM_DYN);
    lstm_main<<<128, 512, SMEM_DYN>>>(x, W_ih, W_hh, b_ih, b_hh);
    bn_stats<<<HH, 256>>>(gamma, beta);
    out_kernel<<<BB/4, 128>>>(fc_w, fc_b, out);
}

// round 11
// speedup vs baseline: 4.3830x; 1.0423x over previous
#include <cuda_runtime.h>
#include <cuda_fp16.h>
#include <cstdint>
typedef uint32_t u32; typedef uint64_t u64;

#define BB 4096
#define TT 512
#define HH 128

// dynamic smem (bytes)
// B: fp16 [144 k][520 cols] stride 1040B (512 used). rows: 0-127 Whh_hi, 128-130 Wih,
//    131 bias, 132-134 Wih (lo partner), 135-143 zero
#define SM_WH 0
#define BSTR  1040
// A: 4 planes [32 rows][152 fp16] stride 304B: buf0(hi,lo), buf1(hi,lo)
//    hi cols 0-127 h_hi, 128-135 x-chunk [x0,x1,x2,1,x0l,x1l,x2l,0], rest 0; lo cols 0-127 h_lo
#define SM_A   149760
#define APLANE 9728
#define SMEM_DYN (149760 + 4*9728)

__device__ __align__(16) float g_h[BB*HH];
__device__ float g_scale[HH], g_shift[HH];

// ---------- helpers ----------
__device__ __forceinline__ u32 smem_u32(const void* p){u32 a;asm("{ .reg .u64 t; cvta.to.shared.u64 t,%1; cvt.u32.u64 %0,t; }":"=r"(a):"l"(p));return a;}
__device__ __forceinline__ float ex2a(float x){float y;asm("ex2.approx.f32 %0,%1;":"=f"(y):"f"(x));return y;}
__device__ __forceinline__ float rcpa(float x){float y;asm("rcp.approx.f32 %0,%1;":"=f"(y):"f"(x));return y;}
__device__ __forceinline__ float sigm(float x){return rcpa(1.0f+ex2a(-1.44269504f*x));}
__device__ __forceinline__ float tanha(float x){return fmaf(-2.0f,rcpa(1.0f+ex2a(2.88539008f*x)),1.0f);}
__device__ __forceinline__ u32 pkh(__half a,__half b){return (u32)__half_as_ushort(a)|((u32)__half_as_ushort(b)<<16);}

#define LDSM4(r,ad) asm volatile("ldmatrix.sync.aligned.m8n8.x4.shared.b16 {%0,%1,%2,%3},[%4];" \
  : "=r"((r)[0]),"=r"((r)[1]),"=r"((r)[2]),"=r"((r)[3]) : "r"(ad))
#define LDSM2T(r,ad) asm volatile("ldmatrix.sync.aligned.m8n8.x2.trans.shared.b16 {%0,%1},[%2];" \
  : "=r"((r)[0]),"=r"((r)[1]) : "r"(ad))
#define MMA(d,a,b) asm volatile("mma.sync.aligned.m16n8k16.row.col.f32.f16.f16.f32 " \
  "{%0,%1,%2,%3},{%4,%5,%6,%7},{%8,%9},{%0,%1,%2,%3};" \
  : "+f"((d)[0]),"+f"((d)[1]),"+f"((d)[2]),"+f"((d)[3]) \
  : "r"((a)[0]),"r"((a)[1]),"r"((a)[2]),"r"((a)[3]),"r"((b)[0]),"r"((b)[1]))

// ---------- persistent mma.sync LSTM (no cluster; CTA = 32 rows x all 512 gate cols) ----------
// 512 threads / 16 warps: warp w -> n strip scol [w*32, w*32+32); both m-tiles (M=32)
// scol = w*32 + g*8 + jl -> gcol = g*128 + w*8 + jl
__global__ void __launch_bounds__(512,1)
lstm_main(const float* __restrict__ x, const float* __restrict__ Wih,
          const float* __restrict__ Whh,
          const float* __restrict__ bih, const float* __restrict__ bhh)
{
    extern __shared__ char smem[];
    const u32 smb = smem_u32(smem);
    const int tid = threadIdx.x, w = tid>>5, lane = tid&31;
    const int b0 = blockIdx.x*32;

    // ---- init B ----
    for (int i = tid; i < 144*512; i += 512) {
        int row = i >> 9, scol = i & 511;
        int g = (scol>>3)&3, wn = scol>>5, jl = scol&7;
        int gcol = g*HH + wn*8 + jl;
        float v;
        if (row < 128)      v = Whh[gcol*HH + row];
        else if (row < 131) v = Wih[gcol*3 + row-128];
        else if (row == 131) v = bih[gcol] + bhh[gcol];
        else if (row < 135) v = Wih[gcol*3 + row-132];
        else                v = 0.0f;
        *(__half*)(smem + SM_WH + row*BSTR + scol*2) = __float2half_rn(v);
    }
    for (int i = tid; i < 4*APLANE/4; i += 512) ((u32*)(smem+SM_A))[i] = 0;  // zero A
    __syncthreads();

    // x(0) into A buf0 x-chunk
    float xr0=0,xr1=0,xr2=0;
    if (tid < 32) {
        const float* xp = x + (u64)(b0+tid)*(TT*3);
        xr0=xp[0]; xr1=xp[1]; xr2=xp[2];
        __half h0=__float2half_rn(xr0), h1=__float2half_rn(xr1), h2=__float2half_rn(xr2);
        __half l0=__float2half_rn(xr0-__half2float(h0));
        __half l1=__float2half_rn(xr1-__half2float(h1));
        __half l2=__float2half_rn(xr2-__half2float(h2));
        u32 off = (u32)SM_A + (u32)tid*304 + 256;
        *(u32*)(smem + off)      = pkh(h0,h1);
        *(u32*)(smem + off + 4)  = pkh(h2,__float2half_rn(1.0f));
        *(u32*)(smem + off + 8)  = pkh(l0,l1);
        *(u32*)(smem + off + 12) = pkh(l2,__ushort_as_half((unsigned short)0));
    }
    __syncthreads();

    // per-thread ldmatrix address components
    const int q = lane>>3, rr = lane&7;
    const u32 rowA_off = (u32)(((q&1)*8+rr)*304 + (q>>1)*16);
    const int Lb = lane & 15;
    const u32 bB_off = (u32)(Lb*BSTR + w*64);
    const int gp = lane>>2, tig = lane&3;
    const int jbase = w*8 + tig*2;

    float creg[8];
#pragma unroll
    for (int i=0;i<8;++i) creg[i]=0.0f;

    for (int t=0; t<TT; ++t) {
        const u32 AHo = (u32)SM_A + (u32)(t&1)*(2*APLANE);
        const u32 AH  = smb + AHo;
        const u32 AL  = AH + APLANE;
        const u32 nxto = (u32)SM_A + (u32)((t+1)&1)*(2*APLANE);
        const bool last = (t==TT-1);

        if (tid < 32 && !last) {  // prefetch x(t+1); consumed below
            const float* xp = x + (u64)(b0+tid)*(TT*3) + (u64)(t+1)*3;
            xr0=xp[0]; xr1=xp[1]; xr2=xp[2];
        }

        // ---- GEMM: 2 m-tiles x 32 cols; kt 0-7: hi+lo terms; kt 8: x-chunk (hi only) ----
        float acc[2][4][4];
#pragma unroll
        for (int mm=0;mm<2;++mm)
#pragma unroll
        for (int g=0;g<4;++g)
#pragma unroll
        for (int r2=0;r2<4;++r2) acc[mm][g][r2]=0.0f;

#pragma unroll
        for (int kt=0; kt<8; ++kt) {
            u32 ah[2][4], al[2][4], bh[4][2];
            u32 aad = AH + (u32)kt*32 + rowA_off;
            u32 lad = AL + (u32)kt*32 + rowA_off;
#pragma unroll
            for (int mm=0;mm<2;++mm) { LDSM4(ah[mm], aad + mm*4864); LDSM4(al[mm], lad + mm*4864); }
            u32 bad = smb + SM_WH + (u32)kt*(16*BSTR) + bB_off;
#pragma unroll
            for (int g=0;g<4;++g) LDSM2T(bh[g], bad + g*16);
#pragma unroll
            for (int mm=0;mm<2;++mm)
#pragma unroll
            for (int g=0;g<4;++g) {
                MMA(acc[mm][g], ah[mm], bh[g]);
                MMA(acc[mm][g], al[mm], bh[g]);
            }
        }
        {   // x-chunk
            u32 ah[2][4], bh[4][2];
            u32 aad = AH + 8*32 + rowA_off;
#pragma unroll
            for (int mm=0;mm<2;++mm) LDSM4(ah[mm], aad + mm*4864);
            u32 bad = smb + SM_WH + (u32)(8*16*BSTR) + bB_off;
#pragma unroll
            for (int g=0;g<4;++g) LDSM2T(bh[g], bad + g*16);
#pragma unroll
            for (int mm=0;mm<2;++mm)
#pragma unroll
            for (int g=0;g<4;++g) MMA(acc[mm][g], ah[mm], bh[g]);
        }

        // ---- epilogue: h -> next A buffer ----
#pragma unroll
        for (int mm=0;mm<2;++mm)
#pragma unroll
        for (int rh=0;rh<2;++rh) {
            int rloc = mm*16 + gp + rh*8;
            float hv[2];
#pragma unroll
            for (int p=0;p<2;++p) {
                int di = rh*2+p;
                float iv=sigm(acc[mm][0][di]);
                float fv=sigm(acc[mm][1][di]);
                float gv=tanha(acc[mm][2][di]);
                float ov=sigm(acc[mm][3][di]);
                int ci=(mm*2+rh)*2+p;
                float cn=fmaf(fv,creg[ci],iv*gv); creg[ci]=cn;
                hv[p]=ov*tanha(cn);
            }
            if (last) {
                *(float2*)&g_h[(u64)(b0+rloc)*HH + jbase] = make_float2(hv[0],hv[1]);
            } else {
                __half h0=__float2half_rn(hv[0]), h1=__float2half_rn(hv[1]);
                __half l0=__float2half_rn(hv[0]-__half2float(h0));
                __half l1=__float2half_rn(hv[1]-__half2float(h1));
                u32 off=(u32)(rloc*304 + jbase*2);
                *(u32*)(smem + nxto + off)          = pkh(h0,h1);
                *(u32*)(smem + nxto + APLANE + off) = pkh(l0,l1);
            }
        }
        if (tid < 32 && !last) {  // x(t+1) -> next A x-chunk
            __half h0=__float2half_rn(xr0), h1=__float2half_rn(xr1), h2=__float2half_rn(xr2);
            __half l0=__float2half_rn(xr0-__half2float(h0));
            __half l1=__float2half_rn(xr1-__half2float(h1));
            __half l2=__float2half_rn(xr2-__half2float(h2));
            u32 off = nxto + (u32)tid*304 + 256;
            *(u32*)(smem + off)      = pkh(h0,h1);
            *(u32*)(smem + off + 4)  = pkh(h2,__float2half_rn(1.0f));
            *(u32*)(smem + off + 8)  = pkh(l0,l1);
            *(u32*)(smem + off + 12) = pkh(l2,__ushort_as_half((unsigned short)0));
        }
        __syncthreads();
    }
}

// ---------- BN stats ----------
__global__ void bn_stats(const float* __restrict__ gamma, const float* __restrict__ beta){
    const int j=blockIdx.x, tid=threadIdx.x;
    __shared__ float red[256]; __shared__ float mean_s;
    float s=0.0f;
    for(int r=tid;r<BB;r+=256) s+=g_h[r*HH+j];
    red[tid]=s; __syncthreads();
    for(int o=128;o>0;o>>=1){ if(tid<o) red[tid]+=red[tid+o]; __syncthreads(); }
    if(tid==0) mean_s=red[0]*(1.0f/BB);
    __syncthreads();
    const float m=mean_s;
    float s2=0.0f;
    for(int r=tid;r<BB;r+=256){ float d=g_h[r*HH+j]-m; s2+=d*d; }
    red[tid]=s2; __syncthreads();
    for(int o=128;o>0;o>>=1){ if(tid<o) red[tid]+=red[tid+o]; __syncthreads(); }
    if(tid==0){ float var=red[0]*(1.0f/BB); float rstd=rsqrtf(var+1e-5f);
        g_scale[j]=rstd*gamma[j]; g_shift[j]=beta[j]-m*rstd*gamma[j]; }
}

// ---------- BN apply + LeakyReLU + FC + sigmoid ----------
__global__ void out_kernel(const float* __restrict__ fcw, const float* __restrict__ fcb,
                           float* __restrict__ out){
    const int lanei=threadIdx.x&31, wp=threadIdx.x>>5;
    const int b=blockIdx.x*4+wp;
    float acc=0.0f;
#pragma unroll
    for(int qq=0;qq<4;qq++){
        int j=lanei+qq*32;
        float v=fmaf(g_h[b*HH+j], g_scale[j], g_shift[j]);
        v=(v>=0.0f)?v:0.01f*v;
        acc=fmaf(v, fcw[j], acc);
    }
#pragma unroll
    for(int o=16;o>0;o>>=1) acc+=__shfl_xor_sync(0xffffffffu,acc,o);
    if(lanei==0) out[b]=sigm(acc+fcb[0]);
}

// ---------- launch ----------
extern "C" void kernel_launch(void* const* d_in, const int* in_sizes, int n_in,
                              void* d_out, int out_size){
    const float* x     = (const float*)d_in[0];
    const float* W_ih  = (const float*)d_in[1];
    const float* W_hh  = (const float*)d_in[2];
    const float* b_ih  = (const float*)d_in[3];
    const float* b_hh  = (const float*)d_in[4];
    const float* gamma = (const float*)d_in[5];
    const float* beta  = (const float*)d_in[6];
    const float* fc_w  = (const float*)d_in[7];
    const float* fc_b  = (const float*)d_in[8];
    float* out = (float*)d_out;

    cudaFuncSetAttribute(lstm_main, cudaFuncAttributeMaxDynamicSharedMemorySize, SMEM_DYN);
    lstm_main<<<BB/32, 512, SMEM_DYN>>>(x, W_ih, W_hh, b_ih, b_hh);
    bn_stats<<<HH, 256>>>(gamma, beta);
    out_kernel<<<BB/4, 128>>>(fc_w, fc_b, out);
}

// round 12
// speedup vs baseline: 5.9282x; 1.3525x over previous
#include <cuda_runtime.h>
#include <cuda_fp16.h>
#include <cstdint>
typedef uint32_t u32; typedef uint64_t u64;

#define BB 4096
#define TT 512
#define HH 128

// dynamic smem (bytes)
// B: fp16 [144 k][520 cols] stride 1040B (512 used). rows: 0-127 Whh_hi, 128-130 Wih,
//    131 bias, 132-134 Wih (x_lo partner), 135-143 zero
#define SM_WH 0
#define BSTR  1040
// A: 2 planes [32 rows][152 fp16] stride 304B: buf0, buf1
//    cols 0-127 h (fp16), 128-135 x-chunk [x0,x1,x2,1,x0l,x1l,x2l,0], rest 0
#define SM_A   149760
#define APLANE 9728
#define SMEM_DYN (149760 + 2*9728)

__device__ __align__(16) float g_h[BB*HH];
__device__ float g_scale[HH], g_shift[HH];

// ---------- helpers ----------
__device__ __forceinline__ u32 smem_u32(const void* p){u32 a;asm("{ .reg .u64 t; cvta.to.shared.u64 t,%1; cvt.u32.u64 %0,t; }":"=r"(a):"l"(p));return a;}
__device__ __forceinline__ float ex2a(float x){float y;asm("ex2.approx.f32 %0,%1;":"=f"(y):"f"(x));return y;}
__device__ __forceinline__ float rcpa(float x){float y;asm("rcp.approx.f32 %0,%1;":"=f"(y):"f"(x));return y;}
__device__ __forceinline__ float sigm(float x){return rcpa(1.0f+ex2a(-1.44269504f*x));}
__device__ __forceinline__ float tanha(float x){return fmaf(-2.0f,rcpa(1.0f+ex2a(2.88539008f*x)),1.0f);}
__device__ __forceinline__ u32 pkh(__half a,__half b){return (u32)__half_as_ushort(a)|((u32)__half_as_ushort(b)<<16);}

#define LDSM4(r,ad) asm volatile("ldmatrix.sync.aligned.m8n8.x4.shared.b16 {%0,%1,%2,%3},[%4];" \
  : "=r"((r)[0]),"=r"((r)[1]),"=r"((r)[2]),"=r"((r)[3]) : "r"(ad))
#define LDSM2T(r,ad) asm volatile("ldmatrix.sync.aligned.m8n8.x2.trans.shared.b16 {%0,%1},[%2];" \
  : "=r"((r)[0]),"=r"((r)[1]) : "r"(ad))
#define MMA(d,a,b) asm volatile("mma.sync.aligned.m16n8k16.row.col.f32.f16.f16.f32 " \
  "{%0,%1,%2,%3},{%4,%5,%6,%7},{%8,%9},{%0,%1,%2,%3};" \
  : "+f"((d)[0]),"+f"((d)[1]),"+f"((d)[2]),"+f"((d)[3]) \
  : "r"((a)[0]),"r"((a)[1]),"r"((a)[2]),"r"((a)[3]),"r"((b)[0]),"r"((b)[1]))

// ---------- persistent mma.sync LSTM (single-term fp16, no cluster) ----------
// CTA = 32 rows x all 512 gate cols; 512 threads / 16 warps
// warp w -> n strip scol [w*32, w*32+32); scol = w*32 + g*8 + jl -> gcol = g*128 + w*8 + jl
__global__ void __launch_bounds__(512,1)
lstm_main(const float* __restrict__ x, const float* __restrict__ Wih,
          const float* __restrict__ Whh,
          const float* __restrict__ bih, const float* __restrict__ bhh)
{
    extern __shared__ char smem[];
    const u32 smb = smem_u32(smem);
    const int tid = threadIdx.x, w = tid>>5, lane = tid&31;
    const int b0 = blockIdx.x*32;

    // ---- init B ----
    for (int i = tid; i < 144*512; i += 512) {
        int row = i >> 9, scol = i & 511;
        int g = (scol>>3)&3, wn = scol>>5, jl = scol&7;
        int gcol = g*HH + wn*8 + jl;
        float v;
        if (row < 128)      v = Whh[gcol*HH + row];
        else if (row < 131) v = Wih[gcol*3 + row-128];
        else if (row == 131) v = bih[gcol] + bhh[gcol];
        else if (row < 135) v = Wih[gcol*3 + row-132];
        else                v = 0.0f;
        *(__half*)(smem + SM_WH + row*BSTR + scol*2) = __float2half_rn(v);
    }
    for (int i = tid; i < 2*APLANE/4; i += 512) ((u32*)(smem+SM_A))[i] = 0;  // zero A
    __syncthreads();

    // x(0) into A buf0 x-chunk
    float xr0=0,xr1=0,xr2=0;
    if (tid < 32) {
        const float* xp = x + (u64)(b0+tid)*(TT*3);
        xr0=xp[0]; xr1=xp[1]; xr2=xp[2];
        __half h0=__float2half_rn(xr0), h1=__float2half_rn(xr1), h2=__float2half_rn(xr2);
        __half l0=__float2half_rn(xr0-__half2float(h0));
        __half l1=__float2half_rn(xr1-__half2float(h1));
        __half l2=__float2half_rn(xr2-__half2float(h2));
        u32 off = (u32)SM_A + (u32)tid*304 + 256;
        *(u32*)(smem + off)      = pkh(h0,h1);
        *(u32*)(smem + off + 4)  = pkh(h2,__float2half_rn(1.0f));
        *(u32*)(smem + off + 8)  = pkh(l0,l1);
        *(u32*)(smem + off + 12) = pkh(l2,__ushort_as_half((unsigned short)0));
    }
    __syncthreads();

    // per-thread ldmatrix address components
    const int q = lane>>3, rr = lane&7;
    const u32 rowA_off = (u32)(((q&1)*8+rr)*304 + (q>>1)*16);
    const int Lb = lane & 15;
    const u32 bB_off = (u32)(Lb*BSTR + w*64);
    const int gp = lane>>2, tig = lane&3;
    const int jbase = w*8 + tig*2;

    float creg[8];
#pragma unroll
    for (int i=0;i<8;++i) creg[i]=0.0f;

    for (int t=0; t<TT; ++t) {
        const u32 AH  = smb + (u32)SM_A + (u32)(t&1)*APLANE;
        const u32 nxto = (u32)SM_A + (u32)((t+1)&1)*APLANE;
        const bool last = (t==TT-1);

        if (tid < 32 && !last) {  // prefetch x(t+1)
            const float* xp = x + (u64)(b0+tid)*(TT*3) + (u64)(t+1)*3;
            xr0=xp[0]; xr1=xp[1]; xr2=xp[2];
        }

        // ---- GEMM: 2 m-tiles x 32 cols, 9 K-chunks, single fp16 term ----
        float acc[2][4][4];
#pragma unroll
        for (int mm=0;mm<2;++mm)
#pragma unroll
        for (int g=0;g<4;++g)
#pragma unroll
        for (int r2=0;r2<4;++r2) acc[mm][g][r2]=0.0f;

#pragma unroll
        for (int kt=0; kt<9; ++kt) {
            u32 ah[2][4], bh[4][2];
            u32 aad = AH + (u32)kt*32 + rowA_off;
#pragma unroll
            for (int mm=0;mm<2;++mm) LDSM4(ah[mm], aad + mm*4864);
            u32 bad = smb + SM_WH + (u32)kt*(16*BSTR) + bB_off;
#pragma unroll
            for (int g=0;g<4;++g) LDSM2T(bh[g], bad + g*16);
#pragma unroll
            for (int mm=0;mm<2;++mm)
#pragma unroll
            for (int g=0;g<4;++g) MMA(acc[mm][g], ah[mm], bh[g]);
        }

        // ---- epilogue: h -> next A buffer ----
#pragma unroll
        for (int mm=0;mm<2;++mm)
#pragma unroll
        for (int rh=0;rh<2;++rh) {
            int rloc = mm*16 + gp + rh*8;
            float hv[2];
#pragma unroll
            for (int p=0;p<2;++p) {
                int di = rh*2+p;
                float iv=sigm(acc[mm][0][di]);
                float fv=sigm(acc[mm][1][di]);
                float gv=tanha(acc[mm][2][di]);
                float ov=sigm(acc[mm][3][di]);
                int ci=(mm*2+rh)*2+p;
                float cn=fmaf(fv,creg[ci],iv*gv); creg[ci]=cn;
                hv[p]=ov*tanha(cn);
            }
            if (last) {
                *(float2*)&g_h[(u64)(b0+rloc)*HH + jbase] = make_float2(hv[0],hv[1]);
            } else {
                u32 hp = pkh(__float2half_rn(hv[0]), __float2half_rn(hv[1]));
                *(u32*)(smem + nxto + (u32)(rloc*304 + jbase*2)) = hp;
            }
        }
        if (tid < 32 && !last) {  // x(t+1) -> next A x-chunk
            __half h0=__float2half_rn(xr0), h1=__float2half_rn(xr1), h2=__float2half_rn(xr2);
            __half l0=__float2half_rn(xr0-__half2float(h0));
            __half l1=__float2half_rn(xr1-__half2float(h1));
            __half l2=__float2half_rn(xr2-__half2float(h2));
            u32 off = nxto + (u32)tid*304 + 256;
            *(u32*)(smem + off)      = pkh(h0,h1);
            *(u32*)(smem + off + 4)  = pkh(h2,__float2half_rn(1.0f));
            *(u32*)(smem + off + 8)  = pkh(l0,l1);
            *(u32*)(smem + off + 12) = pkh(l2,__ushort_as_half((unsigned short)0));
        }
        __syncthreads();
    }
}

// ---------- BN stats ----------
__global__ void bn_stats(const float* __restrict__ gamma, const float* __restrict__ beta){
    const int j=blockIdx.x, tid=threadIdx.x;
    __shared__ float red[256]; __shared__ float mean_s;
    float s=0.0f;
    for(int r=tid;r<BB;r+=256) s+=g_h[r*HH+j];
    red[tid]=s; __syncthreads();
    for(int o=128;o>0;o>>=1){ if(tid<o) red[tid]+=red[tid+o]; __syncthreads(); }
    if(tid==0) mean_s=red[0]*(1.0f/BB);
    __syncthreads();
    const float m=mean_s;
    float s2=0.0f;
    for(int r=tid;r<BB;r+=256){ float d=g_h[r*HH+j]-m; s2+=d*d; }
    red[tid]=s2; __syncthreads();
    for(int o=128;o>0;o>>=1){ if(tid<o) red[tid]+=red[tid+o]; __syncthreads(); }
    if(tid==0){ float var=red[0]*(1.0f/BB); float rstd=rsqrtf(var+1e-5f);
        g_scale[j]=rstd*gamma[j]; g_shift[j]=beta[j]-m*rstd*gamma[j]; }
}

// ---------- BN apply + LeakyReLU + FC + sigmoid ----------
__global__ void out_kernel(const float* __restrict__ fcw, const float* __restrict__ fcb,
                           float* __restrict__ out){
    const int lanei=threadIdx.x&31, wp=threadIdx.x>>5;
    const int b=blockIdx.x*4+wp;
    float acc=0.0f;
#pragma unroll
    for(int qq=0;qq<4;qq++){
        int j=lanei+qq*32;
        float v=fmaf(g_h[b*HH+j], g_scale[j], g_shift[j]);
        v=(v>=0.0f)?v:0.01f*v;
        acc=fmaf(v, fcw[j], acc);
    }
#pragma unroll
    for(int o=16;o>0;o>>=1) acc+=__shfl_xor_sync(0xffffffffu,acc,o);
    if(lanei==0) out[b]=sigm(acc+fcb[0]);
}

// ---------- launch ----------
extern "C" void kernel_launch(void* const* d_in, const int* in_sizes, int n_in,
                              void* d_out, int out_size){
    const float* x     = (const float*)d_in[0];
    const float* W_ih  = (const float*)d_in[1];
    const float* W_hh  = (const float*)d_in[2];
    const float* b_ih  = (const float*)d_in[3];
    const float* b_hh  = (const float*)d_in[4];
    const float* gamma = (const float*)d_in[5];
    const float* beta  = (const float*)d_in[6];
    const float* fc_w  = (const float*)d_in[7];
    const float* fc_b  = (const float*)d_in[8];
    float* out = (float*)d_out;

    cudaFuncSetAttribute(lstm_main, cudaFuncAttributeMaxDynamicSharedMemorySize, SMEM_DYN);
    lstm_main<<<BB/32, 512, SMEM_DYN>>>(x, W_ih, W_hh, b_ih, b_hh);
    bn_stats<<<HH, 256>>>(gamma, beta);
    out_kernel<<<BB/4, 128>>>(fc_w, fc_b, out);
}

// round 13
// speedup vs baseline: 7.9393x; 1.3392x over previous
#include <cuda_runtime.h>
#include <cuda_fp16.h>
#include <cstdint>
typedef uint32_t u32; typedef uint64_t u64;

#define BB 4096
#define TT 512
#define HH 128

// dynamic smem (bytes)
// B: fp16 [144 k][520 cols] stride 1040B (512 used). rows: 0-127 Whh, 128-130 Wih,
//    131 bias, 132-134 Wih (x_lo partner), 135-143 zero
#define SM_WH 0
#define BSTR  1040
// A: 2 planes [32 rows][152 fp16] stride 304B: buf0, buf1
//    cols 0-127 h (fp16), 128-135 x-chunk [x0,x1,x2,1,x0l,x1l,x2l,0], rest 0
#define SM_A   149760
#define APLANE 9728
#define SMEM_DYN (149760 + 2*9728)

__device__ __align__(16) float g_h[BB*HH];
__device__ float g_scale[HH], g_shift[HH];

// ---------- helpers ----------
__device__ __forceinline__ u32 smem_u32(const void* p){u32 a;asm("{ .reg .u64 t; cvta.to.shared.u64 t,%1; cvt.u32.u64 %0,t; }":"=r"(a):"l"(p));return a;}
__device__ __forceinline__ float ex2a(float x){float y;asm("ex2.approx.f32 %0,%1;":"=f"(y):"f"(x));return y;}
__device__ __forceinline__ float rcpa(float x){float y;asm("rcp.approx.f32 %0,%1;":"=f"(y):"f"(x));return y;}
__device__ __forceinline__ float tanhfast(float x){float y;asm("tanh.approx.f32 %0,%1;":"=f"(y):"f"(x));return y;}
__device__ __forceinline__ float sigmfast(float x){return fmaf(tanhfast(0.5f*x),0.5f,0.5f);}
__device__ __forceinline__ float sigm(float x){return rcpa(1.0f+ex2a(-1.44269504f*x));}
__device__ __forceinline__ u32 pkh(__half a,__half b){return (u32)__half_as_ushort(a)|((u32)__half_as_ushort(b)<<16);}

#define LDSM4(r,ad) asm volatile("ldmatrix.sync.aligned.m8n8.x4.shared.b16 {%0,%1,%2,%3},[%4];" \
  : "=r"((r)[0]),"=r"((r)[1]),"=r"((r)[2]),"=r"((r)[3]) : "r"(ad))
#define LDSM4T(r,ad) asm volatile("ldmatrix.sync.aligned.m8n8.x4.trans.shared.b16 {%0,%1,%2,%3},[%4];" \
  : "=r"((r)[0]),"=r"((r)[1]),"=r"((r)[2]),"=r"((r)[3]) : "r"(ad))
#define MMA(d,a,b) asm volatile("mma.sync.aligned.m16n8k16.row.col.f32.f16.f16.f32 " \
  "{%0,%1,%2,%3},{%4,%5,%6,%7},{%8,%9},{%0,%1,%2,%3};" \
  : "+f"((d)[0]),"+f"((d)[1]),"+f"((d)[2]),"+f"((d)[3]) \
  : "r"((a)[0]),"r"((a)[1]),"r"((a)[2]),"r"((a)[3]),"r"((b)[0]),"r"((b)[1]))

// ---------- persistent mma.sync LSTM (single-term fp16, tanh.approx epilogue) ----------
// CTA = 32 rows x all 512 gate cols; 512 threads / 16 warps
// warp w -> scol strip [w*32, w*32+32); scol = w*32 + g*8 + jl -> gcol = g*128 + w*8 + jl
__global__ void __launch_bounds__(512,1)
lstm_main(const float* __restrict__ x, const float* __restrict__ Wih,
          const float* __restrict__ Whh,
          const float* __restrict__ bih, const float* __restrict__ bhh)
{
    extern __shared__ char smem[];
    const u32 smb = smem_u32(smem);
    const int tid = threadIdx.x, w = tid>>5, lane = tid&31;
    const int b0 = blockIdx.x*32;

    // ---- init B ----
    for (int i = tid; i < 144*512; i += 512) {
        int row = i >> 9, scol = i & 511;
        int g = (scol>>3)&3, wn = scol>>5, jl = scol&7;
        int gcol = g*HH + wn*8 + jl;
        float v;
        if (row < 128)      v = Whh[gcol*HH + row];
        else if (row < 131) v = Wih[gcol*3 + row-128];
        else if (row == 131) v = bih[gcol] + bhh[gcol];
        else if (row < 135) v = Wih[gcol*3 + row-132];
        else                v = 0.0f;
        *(__half*)(smem + SM_WH + row*BSTR + scol*2) = __float2half_rn(v);
    }
    for (int i = tid; i < 2*APLANE/4; i += 512) ((u32*)(smem+SM_A))[i] = 0;  // zero A
    __syncthreads();

    // x(0) into A buf0 x-chunk
    float xr0=0,xr1=0,xr2=0;
    if (tid < 32) {
        const float* xp = x + (u64)(b0+tid)*(TT*3);
        xr0=xp[0]; xr1=xp[1]; xr2=xp[2];
        __half h0=__float2half_rn(xr0), h1=__float2half_rn(xr1), h2=__float2half_rn(xr2);
        __half l0=__float2half_rn(xr0-__half2float(h0));
        __half l1=__float2half_rn(xr1-__half2float(h1));
        __half l2=__float2half_rn(xr2-__half2float(h2));
        u32 off = (u32)SM_A + (u32)tid*304 + 256;
        *(u32*)(smem + off)      = pkh(h0,h1);
        *(u32*)(smem + off + 4)  = pkh(h2,__float2half_rn(1.0f));
        *(u32*)(smem + off + 8)  = pkh(l0,l1);
        *(u32*)(smem + off + 12) = pkh(l2,__ushort_as_half((unsigned short)0));
    }
    __syncthreads();

    // per-thread ldmatrix address components
    const int q = lane>>3, rr = lane&7;
    const u32 rowA_off = (u32)(((q&1)*8+rr)*304 + (q>>1)*16);
    // B x4.trans: lane L -> k-row (L&7)+((L>>3)&1)*8, col-group base + (L>>4)
    const u32 bB4_off = (u32)(((lane&7) + ((lane>>3)&1)*8)*BSTR + w*64 + (lane>>4)*16);
    const int gp = lane>>2, tig = lane&3;
    const int jbase = w*8 + tig*2;

    float creg[8];
#pragma unroll
    for (int i=0;i<8;++i) creg[i]=0.0f;

    for (int t=0; t<TT; ++t) {
        const u32 AH  = smb + (u32)SM_A + (u32)(t&1)*APLANE;
        const u32 nxto = (u32)SM_A + (u32)((t+1)&1)*APLANE;
        const bool last = (t==TT-1);

        if (tid < 32 && !last) {  // prefetch x(t+1)
            const float* xp = x + (u64)(b0+tid)*(TT*3) + (u64)(t+1)*3;
            xr0=xp[0]; xr1=xp[1]; xr2=xp[2];
        }

        // ---- GEMM: 2 m-tiles x 32 cols, 9 K-chunks, single fp16 term ----
        float acc[2][4][4];
#pragma unroll
        for (int mm=0;mm<2;++mm)
#pragma unroll
        for (int g=0;g<4;++g)
#pragma unroll
        for (int r2=0;r2<4;++r2) acc[mm][g][r2]=0.0f;

#pragma unroll
        for (int kt=0; kt<9; ++kt) {
            u32 ah[2][4], bh[4][2];
            u32 aad = AH + (u32)kt*32 + rowA_off;
#pragma unroll
            for (int mm=0;mm<2;++mm) LDSM4(ah[mm], aad + mm*4864);
            u32 bad = smb + SM_WH + (u32)kt*(16*BSTR) + bB4_off;
            {   u32 br[4];
                LDSM4T(br, bad);
                bh[0][0]=br[0]; bh[0][1]=br[1]; bh[1][0]=br[2]; bh[1][1]=br[3];
                LDSM4T(br, bad + 32);
                bh[2][0]=br[0]; bh[2][1]=br[1]; bh[3][0]=br[2]; bh[3][1]=br[3];
            }
#pragma unroll
            for (int mm=0;mm<2;++mm)
#pragma unroll
            for (int g=0;g<4;++g) MMA(acc[mm][g], ah[mm], bh[g]);
        }

        // ---- epilogue (tanh.approx): h -> next A buffer ----
#pragma unroll
        for (int mm=0;mm<2;++mm)
#pragma unroll
        for (int rh=0;rh<2;++rh) {
            int rloc = mm*16 + gp + rh*8;
            float hv[2];
#pragma unroll
            for (int p=0;p<2;++p) {
                int di = rh*2+p;
                float iv=sigmfast(acc[mm][0][di]);
                float fv=sigmfast(acc[mm][1][di]);
                float gv=tanhfast(acc[mm][2][di]);
                float ov=sigmfast(acc[mm][3][di]);
                int ci=(mm*2+rh)*2+p;
                float cn=fmaf(fv,creg[ci],iv*gv); creg[ci]=cn;
                hv[p]=ov*tanhfast(cn);
            }
            if (last) {
                *(float2*)&g_h[(u64)(b0+rloc)*HH + jbase] = make_float2(hv[0],hv[1]);
            } else {
                u32 hp = pkh(__float2half_rn(hv[0]), __float2half_rn(hv[1]));
                *(u32*)(smem + nxto + (u32)(rloc*304 + jbase*2)) = hp;
            }
        }
        if (tid < 32 && !last) {  // x(t+1) -> next A x-chunk
            __half h0=__float2half_rn(xr0), h1=__float2half_rn(xr1), h2=__float2half_rn(xr2);
            __half l0=__float2half_rn(xr0-__half2float(h0));
            __half l1=__float2half_rn(xr1-__half2float(h1));
            __half l2=__float2half_rn(xr2-__half2float(h2));
            u32 off = nxto + (u32)tid*304 + 256;
            *(u32*)(smem + off)      = pkh(h0,h1);
            *(u32*)(smem + off + 4)  = pkh(h2,__float2half_rn(1.0f));
            *(u32*)(smem + off + 8)  = pkh(l0,l1);
            *(u32*)(smem + off + 12) = pkh(l2,__ushort_as_half((unsigned short)0));
        }
        __syncthreads();
    }
}

// ---------- BN stats ----------
__global__ void bn_stats(const float* __restrict__ gamma, const float* __restrict__ beta){
    const int j=blockIdx.x, tid=threadIdx.x;
    __shared__ float red[256]; __shared__ float mean_s;
    float s=0.0f;
    for(int r=tid;r<BB;r+=256) s+=g_h[r*HH+j];
    red[tid]=s; __syncthreads();
    for(int o=128;o>0;o>>=1){ if(tid<o) red[tid]+=red[tid+o]; __syncthreads(); }
    if(tid==0) mean_s=red[0]*(1.0f/BB);
    __syncthreads();
    const float m=mean_s;
    float s2=0.0f;
    for(int r=tid;r<BB;r+=256){ float d=g_h[r*HH+j]-m; s2+=d*d; }
    red[tid]=s2; __syncthreads();
    for(int o=128;o>0;o>>=1){ if(tid<o) red[tid]+=red[tid+o]; __syncthreads(); }
    if(tid==0){ float var=red[0]*(1.0f/BB); float rstd=rsqrtf(var+1e-5f);
        g_scale[j]=rstd*gamma[j]; g_shift[j]=beta[j]-m*rstd*gamma[j]; }
}

// ---------- BN apply + LeakyReLU + FC + sigmoid ----------
__global__ void out_kernel(const float* __restrict__ fcw, const float* __restrict__ fcb,
                           float* __restrict__ out){
    const int lanei=threadIdx.x&31, wp=threadIdx.x>>5;
    const int b=blockIdx.x*4+wp;
    float acc=0.0f;
#pragma unroll
    for(int qq=0;qq<4;qq++){
        int j=lanei+qq*32;
        float v=fmaf(g_h[b*HH+j], g_scale[j], g_shift[j]);
        v=(v>=0.0f)?v:0.01f*v;
        acc=fmaf(v, fcw[j], acc);
    }
#pragma unroll
    for(int o=16;o>0;o>>=1) acc+=__shfl_xor_sync(0xffffffffu,acc,o);
    if(lanei==0) out[b]=sigm(acc+fcb[0]);   // exact-ish sigmoid for final output
}

// ---------- launch ----------
extern "C" void kernel_launch(void* const* d_in, const int* in_sizes, int n_in,
                              void* d_out, int out_size){
    const float* x     = (const float*)d_in[0];
    const float* W_ih  = (const float*)d_in[1];
    const float* W_hh  = (const float*)d_in[2];
    const float* b_ih  = (const float*)d_in[3];
    const float* b_hh  = (const float*)d_in[4];
    const float* gamma = (const float*)d_in[5];
    const float* beta  = (const float*)d_in[6];
    const float* fc_w  = (const float*)d_in[7];
    const float* fc_b  = (const float*)d_in[8];
    float* out = (float*)d_out;

    cudaFuncSetAttribute(lstm_main, cudaFuncAttributeMaxDynamicSharedMemorySize, SMEM_DYN);
    lstm_main<<<BB/32, 512, SMEM_DYN>>>(x, W_ih, W_hh, b_ih, b_hh);
    bn_stats<<<HH, 256>>>(gamma, beta);
    out_kernel<<<BB/4, 128>>>(fc_w, fc_b, out);
}

// round 14
// speedup vs baseline: 8.3492x; 1.0516x over previous
#include <cuda_runtime.h>
#include <cuda_fp16.h>
#include <cstdint>
typedef uint32_t u32; typedef uint64_t u64;

#define BB 4096
#define TT 512
#define HH 128

// dynamic smem (bytes)
// W: [512 scol][152 fp16] stride 304B; k 0-127 Whh, 128-130 Wih, 131 bias, 132-134 Wih(xlo partner), 135-143 zero
#define SM_W 0
#define WSTR 304
// h planes: [144 k][40 fp16] stride 80B; k=jcol 0-127 h, 128-135 x-chunk, 136-143 zero; 2 buffers
#define SM_H   155648
#define HSTR   80
#define HPLANE 11520
#define SMEM_DYN (155648 + 2*11520)

__device__ __align__(16) float g_h[BB*HH];
__device__ float g_scale[HH], g_shift[HH];

// ---------- helpers ----------
__device__ __forceinline__ u32 smem_u32(const void* p){u32 a;asm("{ .reg .u64 t; cvta.to.shared.u64 t,%1; cvt.u32.u64 %0,t; }":"=r"(a):"l"(p));return a;}
__device__ __forceinline__ float ex2a(float x){float y;asm("ex2.approx.f32 %0,%1;":"=f"(y):"f"(x));return y;}
__device__ __forceinline__ float rcpa(float x){float y;asm("rcp.approx.f32 %0,%1;":"=f"(y):"f"(x));return y;}
__device__ __forceinline__ float tanhfast(float x){float y;asm("tanh.approx.f32 %0,%1;":"=f"(y):"f"(x));return y;}
__device__ __forceinline__ float sigmfast(float x){return fmaf(tanhfast(0.5f*x),0.5f,0.5f);}
__device__ __forceinline__ float sigm(float x){return rcpa(1.0f+ex2a(-1.44269504f*x));}
__device__ __forceinline__ u32 pkh(__half a,__half b){return (u32)__half_as_ushort(a)|((u32)__half_as_ushort(b)<<16);}

#define LDSM4(r,ad) asm volatile("ldmatrix.sync.aligned.m8n8.x4.shared.b16 {%0,%1,%2,%3},[%4];" \
  : "=r"((r)[0]),"=r"((r)[1]),"=r"((r)[2]),"=r"((r)[3]) : "r"(ad))
#define LDSM4T(r,ad) asm volatile("ldmatrix.sync.aligned.m8n8.x4.trans.shared.b16 {%0,%1,%2,%3},[%4];" \
  : "=r"((r)[0]),"=r"((r)[1]),"=r"((r)[2]),"=r"((r)[3]) : "r"(ad))
#define MMA(d,a,b) asm volatile("mma.sync.aligned.m16n8k16.row.col.f32.f16.f16.f32 " \
  "{%0,%1,%2,%3},{%4,%5,%6,%7},{%8,%9},{%0,%1,%2,%3};" \
  : "+f"((d)[0]),"+f"((d)[1]),"+f"((d)[2]),"+f"((d)[3]) \
  : "r"((a)[0]),"r"((a)[1]),"r"((a)[2]),"r"((a)[3]),"r"((b)[0]),"r"((b)[1]))

// ---------- persistent mma.sync LSTM (W as A-operand resident in registers) ----------
// CTA = 32 rows x 512 gate cols; 512 threads / 16 warps
// warp w: scol strip [w*32, w*32+32); within strip s: gate g=s>>3, jl=s&7 -> gcol=g*128 + w*8 + jl
// D[m=scol][n=row]: thread (gp=lane>>2, tig=lane&3) holds all 4 gates of j=w*8+gp, rows 8nt+2tig+p
__global__ void __launch_bounds__(512,1)
lstm_main(const float* __restrict__ x, const float* __restrict__ Wih,
          const float* __restrict__ Whh,
          const float* __restrict__ bih, const float* __restrict__ bhh)
{
    extern __shared__ char smem[];
    const u32 smb = smem_u32(smem);
    const int tid = threadIdx.x, w = tid>>5, lane = tid&31;
    const int b0 = blockIdx.x*32;

    // ---- init W smem [scol][k] ----
    for (int i = tid; i < 512*144; i += 512) {
        int scol = i / 144, k = i - scol*144;
        int w2 = scol>>5, s = scol&31, g = s>>3, jl = s&7;
        int gcol = g*HH + w2*8 + jl;
        float v;
        if (k < 128)       v = Whh[gcol*HH + k];
        else if (k < 131)  v = Wih[gcol*3 + k-128];
        else if (k == 131) v = bih[gcol] + bhh[gcol];
        else if (k < 135)  v = Wih[gcol*3 + k-132];
        else               v = 0.0f;
        *(__half*)(smem + SM_W + scol*WSTR + k*2) = __float2half_rn(v);
    }
    // zero both h planes (incl. x rows and pad rows)
    for (int i = tid; i < 2*HPLANE/4; i += 512) ((u32*)(smem+SM_H))[i] = 0;
    __syncthreads();

    // x(0) into plane0 x-chunk rows (k=128..135, col=row)
    float xr0=0,xr1=0,xr2=0;
    if (tid < 32) {
        const float* xp = x + (u64)(b0+tid)*(TT*3);
        xr0=xp[0]; xr1=xp[1]; xr2=xp[2];
        __half hx[8];
        hx[0]=__float2half_rn(xr0); hx[1]=__float2half_rn(xr1); hx[2]=__float2half_rn(xr2);
        hx[3]=__float2half_rn(1.0f);
        hx[4]=__float2half_rn(xr0-__half2float(hx[0]));
        hx[5]=__float2half_rn(xr1-__half2float(hx[1]));
        hx[6]=__float2half_rn(xr2-__half2float(hx[2]));
        hx[7]=__ushort_as_half((unsigned short)0);
#pragma unroll
        for (int kk=0;kk<8;++kk)
            *(__half*)(smem + SM_H + (128+kk)*HSTR + tid*2) = hx[kk];
    }
    __syncthreads();

    // per-thread fragment addresses
    const int q = lane>>3, rr = lane&7;
    const u32 aWoff = (u32)(((q&1)*8+rr)*WSTR + (q>>1)*16) + (u32)(w*32)*WSTR;
    const u32 bHoff = (u32)(((lane&7) + ((lane>>3)&1)*8)*HSTR + (lane>>4)*16);
    const int gp = lane>>2, tig = lane&3;
    const int jcol = w*8 + gp;

    // ---- preload W fragments for kt 0..5 into registers ----
    u32 aW[6][2][4];
#pragma unroll
    for (int kt=0;kt<6;++kt)
#pragma unroll
    for (int mt=0;mt<2;++mt)
        LDSM4(aW[kt][mt], smb + SM_W + aWoff + (u32)(mt*16)*WSTR + (u32)kt*32);

    float creg[8];
#pragma unroll
    for (int i=0;i<8;++i) creg[i]=0.0f;

    for (int t=0; t<TT; ++t) {
        const u32 HB  = smb + (u32)SM_H + (u32)(t&1)*HPLANE;
        const u32 nxt = (u32)SM_H + (u32)((t+1)&1)*HPLANE;
        const bool last = (t==TT-1);

        if (tid < 32 && !last) {  // prefetch x(t+1)
            const float* xp = x + (u64)(b0+tid)*(TT*3) + (u64)(t+1)*3;
            xr0=xp[0]; xr1=xp[1]; xr2=xp[2];
        }

        // ---- GEMM: D[32 scol][32 row], 9 K-chunks ----
        float acc[2][4][4];
#pragma unroll
        for (int mt=0;mt<2;++mt)
#pragma unroll
        for (int nt=0;nt<4;++nt)
#pragma unroll
        for (int r2=0;r2<4;++r2) acc[mt][nt][r2]=0.0f;

#pragma unroll
        for (int kt=0; kt<9; ++kt) {
            u32 bh[4][2];
            u32 bad = HB + (u32)kt*(16*HSTR) + bHoff;
            {   u32 br[4];
                LDSM4T(br, bad);
                bh[0][0]=br[0]; bh[0][1]=br[1]; bh[1][0]=br[2]; bh[1][1]=br[3];
                LDSM4T(br, bad + 32);
                bh[2][0]=br[0]; bh[2][1]=br[1]; bh[3][0]=br[2]; bh[3][1]=br[3];
            }
            if (kt < 6) {
#pragma unroll
                for (int mt=0;mt<2;++mt)
#pragma unroll
                for (int nt=0;nt<4;++nt) MMA(acc[mt][nt], aW[kt][mt], bh[nt]);
            } else {
                u32 af[2][4];
#pragma unroll
                for (int mt=0;mt<2;++mt)
                    LDSM4(af[mt], smb + SM_W + aWoff + (u32)(mt*16)*WSTR + (u32)kt*32);
#pragma unroll
                for (int mt=0;mt<2;++mt)
#pragma unroll
                for (int nt=0;nt<4;++nt) MMA(acc[mt][nt], af[mt], bh[nt]);
            }
        }

        // ---- epilogue: thread owns gates i,f (m-tile0 d0/d2) and g,o (m-tile1) of col jcol ----
#pragma unroll
        for (int nt=0;nt<4;++nt) {
            float hv[2];
#pragma unroll
            for (int p=0;p<2;++p) {
                float zi = acc[0][nt][p];      // gate i: m = gp
                float zf = acc[0][nt][2+p];    // gate f: m = gp+8
                float zg = acc[1][nt][p];      // gate g
                float zo = acc[1][nt][2+p];    // gate o
                float iv=sigmfast(zi), fv=sigmfast(zf), gv=tanhfast(zg), ov=sigmfast(zo);
                int ci = nt*2+p;
                float cn=fmaf(fv,creg[ci],iv*gv); creg[ci]=cn;
                hv[p]=ov*tanhfast(cn);
            }
            int row0 = nt*8 + tig*2;
            if (last) {
                g_h[(u64)(b0+row0)*HH + jcol]   = hv[0];
                g_h[(u64)(b0+row0+1)*HH + jcol] = hv[1];
            } else {
                *(u32*)(smem + nxt + (u32)(jcol*HSTR + row0*2))
                    = pkh(__float2half_rn(hv[0]), __float2half_rn(hv[1]));
            }
        }
        if (tid < 32 && !last) {  // x(t+1) -> next plane x rows
            __half hx[8];
            hx[0]=__float2half_rn(xr0); hx[1]=__float2half_rn(xr1); hx[2]=__float2half_rn(xr2);
            hx[3]=__float2half_rn(1.0f);
            hx[4]=__float2half_rn(xr0-__half2float(hx[0]));
            hx[5]=__float2half_rn(xr1-__half2float(hx[1]));
            hx[6]=__float2half_rn(xr2-__half2float(hx[2]));
            hx[7]=__ushort_as_half((unsigned short)0);
#pragma unroll
            for (int kk=0;kk<8;++kk)
                *(__half*)(smem + nxt + (u32)((128+kk)*HSTR + tid*2)) = hx[kk];
        }
        __syncthreads();
    }
}

// ---------- BN stats ----------
__global__ void bn_stats(const float* __restrict__ gamma, const float* __restrict__ beta){
    const int j=blockIdx.x, tid=threadIdx.x;
    __shared__ float red[256]; __shared__ float mean_s;
    float s=0.0f;
    for(int r=tid;r<BB;r+=256) s+=g_h[r*HH+j];
    red[tid]=s; __syncthreads();
    for(int o=128;o>0;o>>=1){ if(tid<o) red[tid]+=red[tid+o]; __syncthreads(); }
    if(tid==0) mean_s=red[0]*(1.0f/BB);
    __syncthreads();
    const float m=mean_s;
    float s2=0.0f;
    for(int r=tid;r<BB;r+=256){ float d=g_h[r*HH+j]-m; s2+=d*d; }
    red[tid]=s2; __syncthreads();
    for(int o=128;o>0;o>>=1){ if(tid<o) red[tid]+=red[tid+o]; __syncthreads(); }
    if(tid==0){ float var=red[0]*(1.0f/BB); float rstd=rsqrtf(var+1e-5f);
        g_scale[j]=rstd*gamma[j]; g_shift[j]=beta[j]-m*rstd*gamma[j]; }
}

// ---------- BN apply + LeakyReLU + FC + sigmoid ----------
__global__ void out_kernel(const float* __restrict__ fcw, const float* __restrict__ fcb,
                           float* __restrict__ out){
    const int lanei=threadIdx.x&31, wp=threadIdx.x>>5;
    const int b=blockIdx.x*4+wp;
    float acc=0.0f;
#pragma unroll
    for(int qq=0;qq<4;qq++){
        int j=lanei+qq*32;
        float v=fmaf(g_h[b*HH+j], g_scale[j], g_shift[j]);
        v=(v>=0.0f)?v:0.01f*v;
        acc=fmaf(v, fcw[j], acc);
    }
#pragma unroll
    for(int o=16;o>0;o>>=1) acc+=__shfl_xor_sync(0xffffffffu,acc,o);
    if(lanei==0) out[b]=sigm(acc+fcb[0]);
}

// ---------- launch ----------
extern "C" void kernel_launch(void* const* d_in, const int* in_sizes, int n_in,
                              void* d_out, int out_size){
    const float* x     = (const float*)d_in[0];
    const float* W_ih  = (const float*)d_in[1];
    const float* W_hh  = (const float*)d_in[2];
    const float* b_ih  = (const float*)d_in[3];
    const float* b_hh  = (const float*)d_in[4];
    const float* gamma = (const float*)d_in[5];
    const float* beta  = (const float*)d_in[6];
    const float* fc_w  = (const float*)d_in[7];
    const float* fc_b  = (const float*)d_in[8];
    float* out = (float*)d_out;

    cudaFuncSetAttribute(lstm_main, cudaFuncAttributeMaxDynamicSharedMemorySize, SMEM_DYN);
    lstm_main<<<BB/32, 512, SMEM_DYN>>>(x, W_ih, W_hh, b_ih, b_hh);
    bn_stats<<<HH, 256>>>(gamma, beta);
    out_kernel<<<BB/4, 128>>>(fc_w, fc_b, out);
}

// round 15
// speedup vs baseline: 9.0703x; 1.0864x over previous
#include <cuda_runtime.h>
#include <cuda_fp16.h>
#include <cstdint>
typedef uint32_t u32; typedef uint64_t u64;

#define BB 4096
#define TT 512
#define HH 128

// dynamic smem (bytes)
// W: [512 scol][152 fp16] stride 304B; k 0-127 Whh, 128-130 Wih, 131 bias, 132-134 Wih(xlo partner), 135-143 zero
#define SM_W 0
#define WSTR 304
// h planes: [144 k][40 fp16] stride 80B; k=jcol 0-127 h, 128-135 x-chunk, 136-143 zero; 2 buffers
#define SM_H   155648
#define HSTR   80
#define HPLANE 11520
#define SMEM_DYN (155648 + 2*11520)

__device__ __align__(16) float g_h[BB*HH];
__device__ float g_scale[HH], g_shift[HH];

// ---------- helpers ----------
__device__ __forceinline__ u32 smem_u32(const void* p){u32 a;asm("{ .reg .u64 t; cvta.to.shared.u64 t,%1; cvt.u32.u64 %0,t; }":"=r"(a):"l"(p));return a;}
__device__ __forceinline__ float ex2a(float x){float y;asm("ex2.approx.f32 %0,%1;":"=f"(y):"f"(x));return y;}
__device__ __forceinline__ float rcpa(float x){float y;asm("rcp.approx.f32 %0,%1;":"=f"(y):"f"(x));return y;}
__device__ __forceinline__ float sigm(float x){return rcpa(1.0f+ex2a(-1.44269504f*x));}
__device__ __forceinline__ __half2 tanh2(__half2 v){
    u32 r, a; a = *(u32*)&v;
    asm("tanh.approx.f16x2 %0,%1;" : "=r"(r) : "r"(a));
    return *(__half2*)&r;
}
__device__ __forceinline__ __half2 sig2(__half2 z){
    const __half2 hlf = __float2half2_rn(0.5f);
    return __hfma2(tanh2(__hmul2(z, hlf)), hlf, hlf);
}
__device__ __forceinline__ u32 pkh(__half a,__half b){return (u32)__half_as_ushort(a)|((u32)__half_as_ushort(b)<<16);}

#define LDSM4(r,ad) asm volatile("ldmatrix.sync.aligned.m8n8.x4.shared.b16 {%0,%1,%2,%3},[%4];" \
  : "=r"((r)[0]),"=r"((r)[1]),"=r"((r)[2]),"=r"((r)[3]) : "r"(ad))
#define LDSM4T(r,ad) asm volatile("ldmatrix.sync.aligned.m8n8.x4.trans.shared.b16 {%0,%1,%2,%3},[%4];" \
  : "=r"((r)[0]),"=r"((r)[1]),"=r"((r)[2]),"=r"((r)[3]) : "r"(ad))
#define MMA(d,a,b) asm volatile("mma.sync.aligned.m16n8k16.row.col.f32.f16.f16.f32 " \
  "{%0,%1,%2,%3},{%4,%5,%6,%7},{%8,%9},{%0,%1,%2,%3};" \
  : "+f"((d)[0]),"+f"((d)[1]),"+f"((d)[2]),"+f"((d)[3]) \
  : "r"((a)[0]),"r"((a)[1]),"r"((a)[2]),"r"((a)[3]),"r"((b)[0]),"r"((b)[1]))

// ---------- persistent mma.sync LSTM (W register-resident, f16x2 packed epilogue) ----------
// CTA = 32 rows x 512 gate cols; 512 threads / 16 warps
// warp w: scol strip [w*32, w*32+32); D[m=scol][n=row]; thread (gp,tig) owns all 4 gates
// of hidden col j=w*8+gp for rows 8nt+2tig+{0,1}
__global__ void __launch_bounds__(512,1)
lstm_main(const float* __restrict__ x, const float* __restrict__ Wih,
          const float* __restrict__ Whh,
          const float* __restrict__ bih, const float* __restrict__ bhh)
{
    extern __shared__ char smem[];
    const u32 smb = smem_u32(smem);
    const int tid = threadIdx.x, w = tid>>5, lane = tid&31;
    const int b0 = blockIdx.x*32;

    // ---- init W smem [scol][k] ----
    for (int i = tid; i < 512*144; i += 512) {
        int scol = i / 144, k = i - scol*144;
        int w2 = scol>>5, s = scol&31, g = s>>3, jl = s&7;
        int gcol = g*HH + w2*8 + jl;
        float v;
        if (k < 128)       v = Whh[gcol*HH + k];
        else if (k < 131)  v = Wih[gcol*3 + k-128];
        else if (k == 131) v = bih[gcol] + bhh[gcol];
        else if (k < 135)  v = Wih[gcol*3 + k-132];
        else               v = 0.0f;
        *(__half*)(smem + SM_W + scol*WSTR + k*2) = __float2half_rn(v);
    }
    for (int i = tid; i < 2*HPLANE/4; i += 512) ((u32*)(smem+SM_H))[i] = 0;
    __syncthreads();

    // x(0) into plane0 x-chunk rows (k=128..135, col=row)
    float xr0=0,xr1=0,xr2=0;
    if (tid < 32) {
        const float* xp = x + (u64)(b0+tid)*(TT*3);
        xr0=xp[0]; xr1=xp[1]; xr2=xp[2];
        __half hx[8];
        hx[0]=__float2half_rn(xr0); hx[1]=__float2half_rn(xr1); hx[2]=__float2half_rn(xr2);
        hx[3]=__float2half_rn(1.0f);
        hx[4]=__float2half_rn(xr0-__half2float(hx[0]));
        hx[5]=__float2half_rn(xr1-__half2float(hx[1]));
        hx[6]=__float2half_rn(xr2-__half2float(hx[2]));
        hx[7]=__ushort_as_half((unsigned short)0);
#pragma unroll
        for (int kk=0;kk<8;++kk)
            *(__half*)(smem + SM_H + (128+kk)*HSTR + tid*2) = hx[kk];
    }
    __syncthreads();

    // per-thread fragment addresses
    const int q = lane>>3, rr = lane&7;
    const u32 aWoff = (u32)(((q&1)*8+rr)*WSTR + (q>>1)*16) + (u32)(w*32)*WSTR;
    const u32 bHoff = (u32)(((lane&7) + ((lane>>3)&1)*8)*HSTR + (lane>>4)*16);
    const int gp = lane>>2, tig = lane&3;
    const int jcol = w*8 + gp;

    // ---- preload W fragments for kt 0..5 into registers ----
    u32 aW[6][2][4];
#pragma unroll
    for (int kt=0;kt<6;++kt)
#pragma unroll
    for (int mt=0;mt<2;++mt)
        LDSM4(aW[kt][mt], smb + SM_W + aWoff + (u32)(mt*16)*WSTR + (u32)kt*32);

    float creg[8];
#pragma unroll
    for (int i=0;i<8;++i) creg[i]=0.0f;

    for (int t=0; t<TT; ++t) {
        const u32 HB  = smb + (u32)SM_H + (u32)(t&1)*HPLANE;
        const u32 nxt = (u32)SM_H + (u32)((t+1)&1)*HPLANE;
        const bool last = (t==TT-1);

        if (tid < 32 && !last) {  // prefetch x(t+1)
            const float* xp = x + (u64)(b0+tid)*(TT*3) + (u64)(t+1)*3;
            xr0=xp[0]; xr1=xp[1]; xr2=xp[2];
        }

        // ---- GEMM: D[32 scol][32 row], 9 K-chunks ----
        float acc[2][4][4];
#pragma unroll
        for (int mt=0;mt<2;++mt)
#pragma unroll
        for (int nt=0;nt<4;++nt)
#pragma unroll
        for (int r2=0;r2<4;++r2) acc[mt][nt][r2]=0.0f;

#pragma unroll
        for (int kt=0; kt<9; ++kt) {
            u32 bh[4][2];
            u32 bad = HB + (u32)kt*(16*HSTR) + bHoff;
            {   u32 br[4];
                LDSM4T(br, bad);
                bh[0][0]=br[0]; bh[0][1]=br[1]; bh[1][0]=br[2]; bh[1][1]=br[3];
                LDSM4T(br, bad + 32);
                bh[2][0]=br[0]; bh[2][1]=br[1]; bh[3][0]=br[2]; bh[3][1]=br[3];
            }
            if (kt < 6) {
#pragma unroll
                for (int mt=0;mt<2;++mt)
#pragma unroll
                for (int nt=0;nt<4;++nt) MMA(acc[mt][nt], aW[kt][mt], bh[nt]);
            } else {
                u32 af[2][4];
#pragma unroll
                for (int mt=0;mt<2;++mt)
                    LDSM4(af[mt], smb + SM_W + aWoff + (u32)(mt*16)*WSTR + (u32)kt*32);
#pragma unroll
                for (int mt=0;mt<2;++mt)
#pragma unroll
                for (int nt=0;nt<4;++nt) MMA(acc[mt][nt], af[mt], bh[nt]);
            }
        }

        // ---- epilogue (f16x2 packed): thread owns gates i,f,g,o of col jcol, row pairs ----
#pragma unroll
        for (int nt=0;nt<4;++nt) {
            __half2 zi = __floats2half2_rn(acc[0][nt][0], acc[0][nt][1]);
            __half2 zf = __floats2half2_rn(acc[0][nt][2], acc[0][nt][3]);
            __half2 zg = __floats2half2_rn(acc[1][nt][0], acc[1][nt][1]);
            __half2 zo = __floats2half2_rn(acc[1][nt][2], acc[1][nt][3]);
            __half2 iv = sig2(zi), fv = sig2(zf), gv = tanh2(zg), ov = sig2(zo);
            float2 ivf = __half22float2(iv), fvf = __half22float2(fv), gvf = __half22float2(gv);
            int ci = nt*2;
            float c0 = fmaf(fvf.x, creg[ci],   ivf.x*gvf.x);
            float c1 = fmaf(fvf.y, creg[ci+1], ivf.y*gvf.y);
            creg[ci]=c0; creg[ci+1]=c1;
            __half2 hh = __hmul2(ov, tanh2(__floats2half2_rn(c0, c1)));
            int row0 = nt*8 + tig*2;
            if (last) {
                float2 hf = __half22float2(hh);
                g_h[(u64)(b0+row0)*HH + jcol]   = hf.x;
                g_h[(u64)(b0+row0+1)*HH + jcol] = hf.y;
            } else {
                *(u32*)(smem + nxt + (u32)(jcol*HSTR + row0*2)) = *(u32*)&hh;
            }
        }
        if (tid < 32 && !last) {  // x(t+1) -> next plane x rows
            __half hx[8];
            hx[0]=__float2half_rn(xr0); hx[1]=__float2half_rn(xr1); hx[2]=__float2half_rn(xr2);
            hx[3]=__float2half_rn(1.0f);
            hx[4]=__float2half_rn(xr0-__half2float(hx[0]));
            hx[5]=__float2half_rn(xr1-__half2float(hx[1]));
            hx[6]=__float2half_rn(xr2-__half2float(hx[2]));
            hx[7]=__ushort_as_half((unsigned short)0);
#pragma unroll
            for (int kk=0;kk<8;++kk)
                *(__half*)(smem + nxt + (u32)((128+kk)*HSTR + tid*2)) = hx[kk];
        }
        __syncthreads();
    }
}

// ---------- BN stats ----------
__global__ void bn_stats(const float* __restrict__ gamma, const float* __restrict__ beta){
    const int j=blockIdx.x, tid=threadIdx.x;
    __shared__ float red[256]; __shared__ float mean_s;
    float s=0.0f;
    for(int r=tid;r<BB;r+=256) s+=g_h[r*HH+j];
    red[tid]=s; __syncthreads();
    for(int o=128;o>0;o>>=1){ if(tid<o) red[tid]+=red[tid+o]; __syncthreads(); }
    if(tid==0) mean_s=red[0]*(1.0f/BB);
    __syncthreads();
    const float m=mean_s;
    float s2=0.0f;
    for(int r=tid;r<BB;r+=256){ float d=g_h[r*HH+j]-m; s2+=d*d; }
    red[tid]=s2; __syncthreads();
    for(int o=128;o>0;o>>=1){ if(tid<o) red[tid]+=red[tid+o]; __syncthreads(); }
    if(tid==0){ float var=red[0]*(1.0f/BB); float rstd=rsqrtf(var+1e-5f);
        g_scale[j]=rstd*gamma[j]; g_shift[j]=beta[j]-m*rstd*gamma[j]; }
}

// ---------- BN apply + LeakyReLU + FC + sigmoid ----------
__global__ void out_kernel(const float* __restrict__ fcw, const float* __restrict__ fcb,
                           float* __restrict__ out){
    const int lanei=threadIdx.x&31, wp=threadIdx.x>>5;
    const int b=blockIdx.x*4+wp;
    float acc=0.0f;
#pragma unroll
    for(int qq=0;qq<4;qq++){
        int j=lanei+qq*32;
        float v=fmaf(g_h[b*HH+j], g_scale[j], g_shift[j]);
        v=(v>=0.0f)?v:0.01f*v;
        acc=fmaf(v, fcw[j], acc);
    }
#pragma unroll
    for(int o=16;o>0;o>>=1) acc+=__shfl_xor_sync(0xffffffffu,acc,o);
    if(lanei==0) out[b]=sigm(acc+fcb[0]);
}

// ---------- launch ----------
extern "C" void kernel_launch(void* const* d_in, const int* in_sizes, int n_in,
                              void* d_out, int out_size){
    const float* x     = (const float*)d_in[0];
    const float* W_ih  = (const float*)d_in[1];
    const float* W_hh  = (const float*)d_in[2];
    const float* b_ih  = (const float*)d_in[3];
    const float* b_hh  = (const float*)d_in[4];
    const float* gamma = (const float*)d_in[5];
    const float* beta  = (const float*)d_in[6];
    const float* fc_w  = (const float*)d_in[7];
    const float* fc_b  = (const float*)d_in[8];
    float* out = (float*)d_out;

    cudaFuncSetAttribute(lstm_main, cudaFuncAttributeMaxDynamicSharedMemorySize, SMEM_DYN);
    lstm_main<<<BB/32, 512, SMEM_DYN>>>(x, W_ih, W_hh, b_ih, b_hh);
    bn_stats<<<HH, 256>>>(gamma, beta);
    out_kernel<<<BB/4, 128>>>(fc_w, fc_b, out);
}

// round 16
// speedup vs baseline: 9.9800x; 1.1003x over previous
#include <cuda_runtime.h>
#include <cuda_fp16.h>
#include <cstdint>
typedef uint32_t u32; typedef uint64_t u64;

#define BB 4096
#define TT 512
#define HH 128

// dynamic smem (bytes)
// W: [512 scol][152 fp16] stride 304B; k 0-127 Whh, 128-130 Wih, 131 bias, 132-134 Wih(xlo), 135-143 zero
#define SM_W 0
#define WSTR 304
// h planes: [144 k][40 fp16] stride 80B; k=jcol 0-127 h, 128-135 x-chunk, 136-143 zero; 2 buffers
#define SM_H   155648
#define HSTR   80
#define HPLANE 11520
#define SMEM_DYN (155648 + 2*11520)

__device__ __align__(16) float g_h[BB*HH];
__device__ float g_scale[HH], g_shift[HH];

// ---------- helpers ----------
__device__ __forceinline__ u32 smem_u32(const void* p){u32 a;asm("{ .reg .u64 t; cvta.to.shared.u64 t,%1; cvt.u32.u64 %0,t; }":"=r"(a):"l"(p));return a;}
__device__ __forceinline__ float ex2a(float x){float y;asm("ex2.approx.f32 %0,%1;":"=f"(y):"f"(x));return y;}
__device__ __forceinline__ float rcpa(float x){float y;asm("rcp.approx.f32 %0,%1;":"=f"(y):"f"(x));return y;}
__device__ __forceinline__ float sigm(float x){return rcpa(1.0f+ex2a(-1.44269504f*x));}
__device__ __forceinline__ __half2 tanh2(__half2 v){
    u32 r, a; a = *(u32*)&v;
    asm("tanh.approx.f16x2 %0,%1;" : "=r"(r) : "r"(a));
    return *(__half2*)&r;
}
__device__ __forceinline__ __half2 sig2(__half2 z){
    const __half2 hlf = __float2half2_rn(0.5f);
    return __hfma2(tanh2(__hmul2(z, hlf)), hlf, hlf);
}

#define LDSM4(r,ad) asm volatile("ldmatrix.sync.aligned.m8n8.x4.shared.b16 {%0,%1,%2,%3},[%4];" \
  : "=r"((r)[0]),"=r"((r)[1]),"=r"((r)[2]),"=r"((r)[3]) : "r"(ad))
#define LDSM4T(r,ad) asm volatile("ldmatrix.sync.aligned.m8n8.x4.trans.shared.b16 {%0,%1,%2,%3},[%4];" \
  : "=r"((r)[0]),"=r"((r)[1]),"=r"((r)[2]),"=r"((r)[3]) : "r"(ad))
#define MMA(d,a,b) asm volatile("mma.sync.aligned.m16n8k16.row.col.f32.f16.f16.f32 " \
  "{%0,%1,%2,%3},{%4,%5,%6,%7},{%8,%9},{%0,%1,%2,%3};" \
  : "+f"((d)[0]),"+f"((d)[1]),"+f"((d)[2]),"+f"((d)[3]) \
  : "r"((a)[0]),"r"((a)[1]),"r"((a)[2]),"r"((a)[3]),"r"((b)[0]),"r"((b)[1]))

// ---------- persistent mma.sync LSTM ----------
// CTA = 32 rows x 512 gate cols; 512 threads / 16 warps
// warp w: scol strip [w*32, w*32+32); D[m=scol][n=row]; thread (gp,tig) owns all 4 gates of
// hidden col j=w*8+gp, rows 8nt+2tig+{0,1}. Step split into two nt-half passes for
// cross-warp tensor/MUFU overlap; ALL 9 W k-chunk fragments live in registers.
__global__ void __launch_bounds__(512,1)
lstm_main(const float* __restrict__ x, const float* __restrict__ Wih,
          const float* __restrict__ Whh,
          const float* __restrict__ bih, const float* __restrict__ bhh)
{
    extern __shared__ char smem[];
    const u32 smb = smem_u32(smem);
    const int tid = threadIdx.x, w = tid>>5, lane = tid&31;
    const int b0 = blockIdx.x*32;

    // ---- init W smem [scol][k] ----
    for (int i = tid; i < 512*144; i += 512) {
        int scol = i / 144, k = i - scol*144;
        int w2 = scol>>5, s = scol&31, g = s>>3, jl = s&7;
        int gcol = g*HH + w2*8 + jl;
        float v;
        if (k < 128)       v = Whh[gcol*HH + k];
        else if (k < 131)  v = Wih[gcol*3 + k-128];
        else if (k == 131) v = bih[gcol] + bhh[gcol];
        else if (k < 135)  v = Wih[gcol*3 + k-132];
        else               v = 0.0f;
        *(__half*)(smem + SM_W + scol*WSTR + k*2) = __float2half_rn(v);
    }
    for (int i = tid; i < 2*HPLANE/4; i += 512) ((u32*)(smem+SM_H))[i] = 0;
    __syncthreads();

    // x(0) into plane0 x-chunk rows (k=128..135, col=row)
    float xr0=0,xr1=0,xr2=0;
    if (tid < 32) {
        const float* xp = x + (u64)(b0+tid)*(TT*3);
        xr0=xp[0]; xr1=xp[1]; xr2=xp[2];
        __half hx[8];
        hx[0]=__float2half_rn(xr0); hx[1]=__float2half_rn(xr1); hx[2]=__float2half_rn(xr2);
        hx[3]=__float2half_rn(1.0f);
        hx[4]=__float2half_rn(xr0-__half2float(hx[0]));
        hx[5]=__float2half_rn(xr1-__half2float(hx[1]));
        hx[6]=__float2half_rn(xr2-__half2float(hx[2]));
        hx[7]=__ushort_as_half((unsigned short)0);
#pragma unroll
        for (int kk=0;kk<8;++kk)
            *(__half*)(smem + SM_H + (128+kk)*HSTR + tid*2) = hx[kk];
    }
    __syncthreads();

    // per-thread fragment addresses
    const int q = lane>>3, rr = lane&7;
    const u32 aWoff = (u32)(((q&1)*8+rr)*WSTR + (q>>1)*16) + (u32)(w*32)*WSTR;
    const u32 bHoff = (u32)(((lane&7) + ((lane>>3)&1)*8)*HSTR + (lane>>4)*16);
    const int gp = lane>>2, tig = lane&3;
    const int jcol = w*8 + gp;

    // ---- preload ALL 9 W k-chunk fragments into registers (72 regs) ----
    u32 aW[9][2][4];
#pragma unroll
    for (int kt=0;kt<9;++kt)
#pragma unroll
    for (int mt=0;mt<2;++mt)
        LDSM4(aW[kt][mt], smb + SM_W + aWoff + (u32)(mt*16)*WSTR + (u32)kt*32);

    float creg[8];
#pragma unroll
    for (int i=0;i<8;++i) creg[i]=0.0f;

    for (int t=0; t<TT; ++t) {
        const u32 HB  = smb + (u32)SM_H + (u32)(t&1)*HPLANE;
        const u32 nxt = (u32)SM_H + (u32)((t+1)&1)*HPLANE;
        const bool last = (t==TT-1);

        if (tid < 32 && !last) {  // prefetch x(t+1)
            const float* xp = x + (u64)(b0+tid)*(TT*3) + (u64)(t+1)*3;
            xr0=xp[0]; xr1=xp[1]; xr2=xp[2];
        }

        // ---- two nt-half passes; epilogue(pass0) overlaps GEMM(pass1) across warps ----
#pragma unroll
        for (int ph=0; ph<2; ++ph) {
            float acc[2][2][4];
#pragma unroll
            for (int mt=0;mt<2;++mt)
#pragma unroll
            for (int nl=0;nl<2;++nl)
#pragma unroll
            for (int r2=0;r2<4;++r2) acc[mt][nl][r2]=0.0f;

#pragma unroll
            for (int kt=0; kt<9; ++kt) {
                u32 br[4];
                LDSM4T(br, HB + (u32)kt*(16*HSTR) + bHoff + (u32)ph*32);
                u32 b0f[2] = {br[0], br[1]};
                u32 b1f[2] = {br[2], br[3]};
#pragma unroll
                for (int mt=0;mt<2;++mt) {
                    MMA(acc[mt][0], aW[kt][mt], b0f);
                    MMA(acc[mt][1], aW[kt][mt], b1f);
                }
            }

            // epilogue for this half (nt = ph*2 + nl)
#pragma unroll
            for (int nl=0;nl<2;++nl) {
                int nt = ph*2 + nl;
                __half2 zi = __floats2half2_rn(acc[0][nl][0], acc[0][nl][1]);
                __half2 zf = __floats2half2_rn(acc[0][nl][2], acc[0][nl][3]);
                __half2 zg = __floats2half2_rn(acc[1][nl][0], acc[1][nl][1]);
                __half2 zo = __floats2half2_rn(acc[1][nl][2], acc[1][nl][3]);
                __half2 iv = sig2(zi), fv = sig2(zf), gv = tanh2(zg), ov = sig2(zo);
                float2 ivf = __half22float2(iv), fvf = __half22float2(fv), gvf = __half22float2(gv);
                int ci = nt*2;
                float c0 = fmaf(fvf.x, creg[ci],   ivf.x*gvf.x);
                float c1 = fmaf(fvf.y, creg[ci+1], ivf.y*gvf.y);
                creg[ci]=c0; creg[ci+1]=c1;
                __half2 hh = __hmul2(ov, tanh2(__floats2half2_rn(c0, c1)));
                int row0 = nt*8 + tig*2;
                if (last) {
                    float2 hf = __half22float2(hh);
                    g_h[(u64)(b0+row0)*HH + jcol]   = hf.x;
                    g_h[(u64)(b0+row0+1)*HH + jcol] = hf.y;
                } else {
                    *(u32*)(smem + nxt + (u32)(jcol*HSTR + row0*2)) = *(u32*)&hh;
                }
            }
        }

        if (tid < 32 && !last) {  // x(t+1) -> next plane x rows
            __half hx[8];
            hx[0]=__float2half_rn(xr0); hx[1]=__float2half_rn(xr1); hx[2]=__float2half_rn(xr2);
            hx[3]=__float2half_rn(1.0f);
            hx[4]=__float2half_rn(xr0-__half2float(hx[0]));
            hx[5]=__float2half_rn(xr1-__half2float(hx[1]));
            hx[6]=__float2half_rn(xr2-__half2float(hx[2]));
            hx[7]=__ushort_as_half((unsigned short)0);
#pragma unroll
            for (int kk=0;kk<8;++kk)
                *(__half*)(smem + nxt + (u32)((128+kk)*HSTR + tid*2)) = hx[kk];
        }
        __syncthreads();
    }
}

// ---------- BN stats ----------
__global__ void bn_stats(const float* __restrict__ gamma, const float* __restrict__ beta){
    const int j=blockIdx.x, tid=threadIdx.x;
    __shared__ float red[256]; __shared__ float mean_s;
    float s=0.0f;
    for(int r=tid;r<BB;r+=256) s+=g_h[r*HH+j];
    red[tid]=s; __syncthreads();
    for(int o=128;o>0;o>>=1){ if(tid<o) red[tid]+=red[tid+o]; __syncthreads(); }
    if(tid==0) mean_s=red[0]*(1.0f/BB);
    __syncthreads();
    const float m=mean_s;
    float s2=0.0f;
    for(int r=tid;r<BB;r+=256){ float d=g_h[r*HH+j]-m; s2+=d*d; }
    red[tid]=s2; __syncthreads();
    for(int o=128;o>0;o>>=1){ if(tid<o) red[tid]+=red[tid+o]; __syncthreads(); }
    if(tid==0){ float var=red[0]*(1.0f/BB); float rstd=rsqrtf(var+1e-5f);
        g_scale[j]=rstd*gamma[j]; g_shift[j]=beta[j]-m*rstd*gamma[j]; }
}

// ---------- BN apply + LeakyReLU + FC + sigmoid ----------
__global__ void out_kernel(const float* __restrict__ fcw, const float* __restrict__ fcb,
                           float* __restrict__ out){
    const int lanei=threadIdx.x&31, wp=threadIdx.x>>5;
    const int b=blockIdx.x*4+wp;
    float acc=0.0f;
#pragma unroll
    for(int qq=0;qq<4;qq++){
        int j=lanei+qq*32;
        float v=fmaf(g_h[b*HH+j], g_scale[j], g_shift[j]);
        v=(v>=0.0f)?v:0.01f*v;
        acc=fmaf(v, fcw[j], acc);
    }
#pragma unroll
    for(int o=16;o>0;o>>=1) acc+=__shfl_xor_sync(0xffffffffu,acc,o);
    if(lanei==0) out[b]=sigm(acc+fcb[0]);
}

// ---------- launch ----------
extern "C" void kernel_launch(void* const* d_in, const int* in_sizes, int n_in,
                              void* d_out, int out_size){
    const float* x     = (const float*)d_in[0];
    const float* W_ih  = (const float*)d_in[1];
    const float* W_hh  = (const float*)d_in[2];
    const float* b_ih  = (const float*)d_in[3];
    const float* b_hh  = (const float*)d_in[4];
    const float* gamma = (const float*)d_in[5];
    const float* beta  = (const float*)d_in[6];
    const float* fc_w  = (const float*)d_in[7];
    const float* fc_b  = (const float*)d_in[8];
    float* out = (float*)d_out;

    cudaFuncSetAttribute(lstm_main, cudaFuncAttributeMaxDynamicSharedMemorySize, SMEM_DYN);
    lstm_main<<<BB/32, 512, SMEM_DYN>>>(x, W_ih, W_hh, b_ih, b_hh);
    bn_stats<<<HH, 256>>>(gamma, beta);
    out_kernel<<<BB/4, 128>>>(fc_w, fc_b, out);
}

// round 17
// speedup vs baseline: 9.9982x; 1.0018x over previous
#include <cuda_runtime.h>
#include <cuda_fp16.h>
#include <cstdint>
typedef uint32_t u32; typedef uint64_t u64;

#define BB 4096
#define TT 512
#define HH 128

// dynamic smem (bytes)
// W: [512 scol][152 fp16] stride 304B; k 0-127 Whh, 128-130 Wih, 131 bias, 132-134 Wih(xlo), 135-143 zero
#define SM_W 0
#define WSTR 304
// h planes: [144 k][40 fp16] stride 80B; k=jcol 0-127 h, 128-135 x-chunk, 136-143 zero; 2 buffers
#define SM_H   155648
#define HSTR   80
#define HPLANE 11520
#define SMEM_DYN (155648 + 2*11520)

__device__ __align__(16) float g_h[BB*HH];
__device__ float g_scale[HH], g_shift[HH];

// ---------- helpers ----------
__device__ __forceinline__ u32 smem_u32(const void* p){u32 a;asm("{ .reg .u64 t; cvta.to.shared.u64 t,%1; cvt.u32.u64 %0,t; }":"=r"(a):"l"(p));return a;}
__device__ __forceinline__ float ex2a(float x){float y;asm("ex2.approx.f32 %0,%1;":"=f"(y):"f"(x));return y;}
__device__ __forceinline__ float rcpa(float x){float y;asm("rcp.approx.f32 %0,%1;":"=f"(y):"f"(x));return y;}
__device__ __forceinline__ float sigm(float x){return rcpa(1.0f+ex2a(-1.44269504f*x));}
__device__ __forceinline__ __half2 tanh2(__half2 v){
    u32 r, a; a = *(u32*)&v;
    asm("tanh.approx.f16x2 %0,%1;" : "=r"(r) : "r"(a));
    return *(__half2*)&r;
}
__device__ __forceinline__ __half2 sig2(__half2 z){
    const __half2 hlf = __float2half2_rn(0.5f);
    return __hfma2(tanh2(__hmul2(z, hlf)), hlf, hlf);
}

#define LDSM4(r,ad) asm volatile("ldmatrix.sync.aligned.m8n8.x4.shared.b16 {%0,%1,%2,%3},[%4];" \
  : "=r"((r)[0]),"=r"((r)[1]),"=r"((r)[2]),"=r"((r)[3]) : "r"(ad))
#define LDSM2T(r,ad) asm volatile("ldmatrix.sync.aligned.m8n8.x2.trans.shared.b16 {%0,%1},[%2];" \
  : "=r"((r)[0]),"=r"((r)[1]) : "r"(ad))
#define LDSM1T(r,ad) asm volatile("ldmatrix.sync.aligned.m8n8.x1.trans.shared.b16 {%0},[%1];" \
  : "=r"(r) : "r"(ad))
#define MMA(d,a,b) asm volatile("mma.sync.aligned.m16n8k16.row.col.f32.f16.f16.f32 " \
  "{%0,%1,%2,%3},{%4,%5,%6,%7},{%8,%9},{%0,%1,%2,%3};" \
  : "+f"((d)[0]),"+f"((d)[1]),"+f"((d)[2]),"+f"((d)[3]) \
  : "r"((a)[0]),"r"((a)[1]),"r"((a)[2]),"r"((a)[3]),"r"((b)[0]),"r"((b)[1]))
#define MMA8(d,a,b) asm volatile("mma.sync.aligned.m16n8k8.row.col.f32.f16.f16.f32 " \
  "{%0,%1,%2,%3},{%4,%5},{%6},{%0,%1,%2,%3};" \
  : "+f"((d)[0]),"+f"((d)[1]),"+f"((d)[2]),"+f"((d)[3]) \
  : "r"((a)[0]),"r"((a)[1]),"r"(b))

// ---------- persistent mma.sync LSTM ----------
// CTA = 32 rows x 512 gate cols; 512 threads / 16 warps
// warp w: scol strip [w*32, w*32+32); D[m=scol][n=row]; thread (gp,tig) owns all 4 gates of
// hidden col j=w*8+gp, rows 8nt+2tig+{0,1}. Step = FOUR nt-passes (fine tensor/MUFU interleave);
// all 9 W k-chunk fragments register-resident; x-chunk via m16n8k8.
__global__ void __launch_bounds__(512,1)
lstm_main(const float* __restrict__ x, const float* __restrict__ Wih,
          const float* __restrict__ Whh,
          const float* __restrict__ bih, const float* __restrict__ bhh)
{
    extern __shared__ char smem[];
    const u32 smb = smem_u32(smem);
    const int tid = threadIdx.x, w = tid>>5, lane = tid&31;
    const int b0 = blockIdx.x*32;

    // ---- init W smem [scol][k] ----
    for (int i = tid; i < 512*144; i += 512) {
        int scol = i / 144, k = i - scol*144;
        int w2 = scol>>5, s = scol&31, g = s>>3, jl = s&7;
        int gcol = g*HH + w2*8 + jl;
        float v;
        if (k < 128)       v = Whh[gcol*HH + k];
        else if (k < 131)  v = Wih[gcol*3 + k-128];
        else if (k == 131) v = bih[gcol] + bhh[gcol];
        else if (k < 135)  v = Wih[gcol*3 + k-132];
        else               v = 0.0f;
        *(__half*)(smem + SM_W + scol*WSTR + k*2) = __float2half_rn(v);
    }
    for (int i = tid; i < 2*HPLANE/4; i += 512) ((u32*)(smem+SM_H))[i] = 0;
    __syncthreads();

    // x(0) into plane0 x-chunk rows (k=128..135, col=row)
    float xr0=0,xr1=0,xr2=0;
    if (tid < 32) {
        const float* xp = x + (u64)(b0+tid)*(TT*3);
        xr0=xp[0]; xr1=xp[1]; xr2=xp[2];
        __half hx[8];
        hx[0]=__float2half_rn(xr0); hx[1]=__float2half_rn(xr1); hx[2]=__float2half_rn(xr2);
        hx[3]=__float2half_rn(1.0f);
        hx[4]=__float2half_rn(xr0-__half2float(hx[0]));
        hx[5]=__float2half_rn(xr1-__half2float(hx[1]));
        hx[6]=__float2half_rn(xr2-__half2float(hx[2]));
        hx[7]=__ushort_as_half((unsigned short)0);
#pragma unroll
        for (int kk=0;kk<8;++kk)
            *(__half*)(smem + SM_H + (128+kk)*HSTR + tid*2) = hx[kk];
    }
    __syncthreads();

    // per-thread fragment addresses
    const int q = lane>>3, rr = lane&7;
    const u32 aWoff = (u32)(((q&1)*8+rr)*WSTR + (q>>1)*16) + (u32)(w*32)*WSTR;
    const u32 bHoff = (u32)(((lane&7) + ((lane>>3)&1)*8)*HSTR);   // x2.trans: lanes 0-15 matter
    const u32 bXoff = (u32)((lane&7)*HSTR);                        // x1.trans: lanes 0-7 matter
    const int gp = lane>>2, tig = lane&3;
    const int jcol = w*8 + gp;

    // ---- preload ALL 9 W k-chunk fragments into registers ----
    u32 aW[9][2][4];
#pragma unroll
    for (int kt=0;kt<9;++kt)
#pragma unroll
    for (int mt=0;mt<2;++mt)
        LDSM4(aW[kt][mt], smb + SM_W + aWoff + (u32)(mt*16)*WSTR + (u32)kt*32);

    float creg[8];
#pragma unroll
    for (int i=0;i<8;++i) creg[i]=0.0f;

    for (int t=0; t<TT; ++t) {
        const u32 HB  = smb + (u32)SM_H + (u32)(t&1)*HPLANE;
        const u32 nxt = (u32)SM_H + (u32)((t+1)&1)*HPLANE;
        const bool last = (t==TT-1);

        if (tid < 32 && !last) {  // prefetch x(t+1)
            const float* xp = x + (u64)(b0+tid)*(TT*3) + (u64)(t+1)*3;
            xr0=xp[0]; xr1=xp[1]; xr2=xp[2];
        }

        // ---- four nt-passes; epilogue(i) overlaps GEMM(i+1) ----
#pragma unroll
        for (int nt=0; nt<4; ++nt) {
            float acc[2][4];
#pragma unroll
            for (int mt=0;mt<2;++mt)
#pragma unroll
            for (int r2=0;r2<4;++r2) acc[mt][r2]=0.0f;

#pragma unroll
            for (int kt=0; kt<8; ++kt) {
                u32 bf[2];
                LDSM2T(bf, HB + (u32)kt*(16*HSTR) + bHoff + (u32)nt*16);
#pragma unroll
                for (int mt=0;mt<2;++mt) MMA(acc[mt], aW[kt][mt], bf);
            }
            {   // x-chunk: 8 real k rows -> m16n8k8
                u32 bx;
                LDSM1T(bx, HB + (u32)(128*HSTR) + bXoff + (u32)nt*16);
#pragma unroll
                for (int mt=0;mt<2;++mt) MMA8(acc[mt], aW[8][mt], bx);
            }

            // epilogue for this nt
            __half2 zi = __floats2half2_rn(acc[0][0], acc[0][1]);
            __half2 zf = __floats2half2_rn(acc[0][2], acc[0][3]);
            __half2 zg = __floats2half2_rn(acc[1][0], acc[1][1]);
            __half2 zo = __floats2half2_rn(acc[1][2], acc[1][3]);
            __half2 iv = sig2(zi), fv = sig2(zf), gv = tanh2(zg), ov = sig2(zo);
            float2 ivf = __half22float2(iv), fvf = __half22float2(fv), gvf = __half22float2(gv);
            int ci = nt*2;
            float c0 = fmaf(fvf.x, creg[ci],   ivf.x*gvf.x);
            float c1 = fmaf(fvf.y, creg[ci+1], ivf.y*gvf.y);
            creg[ci]=c0; creg[ci+1]=c1;
            __half2 hh = __hmul2(ov, tanh2(__floats2half2_rn(c0, c1)));
            int row0 = nt*8 + tig*2;
            if (last) {
                float2 hf = __half22float2(hh);
                g_h[(u64)(b0+row0)*HH + jcol]   = hf.x;
                g_h[(u64)(b0+row0+1)*HH + jcol] = hf.y;
            } else {
                *(u32*)(smem + nxt + (u32)(jcol*HSTR + row0*2)) = *(u32*)&hh;
            }
        }

        if (tid < 32 && !last) {  // x(t+1) -> next plane x rows
            __half hx[8];
            hx[0]=__float2half_rn(xr0); hx[1]=__float2half_rn(xr1); hx[2]=__float2half_rn(xr2);
            hx[3]=__float2half_rn(1.0f);
            hx[4]=__float2half_rn(xr0-__half2float(hx[0]));
            hx[5]=__float2half_rn(xr1-__half2float(hx[1]));
            hx[6]=__float2half_rn(xr2-__half2float(hx[2]));
            hx[7]=__ushort_as_half((unsigned short)0);
#pragma unroll
            for (int kk=0;kk<8;++kk)
                *(__half*)(smem + nxt + (u32)((128+kk)*HSTR + tid*2)) = hx[kk];
        }
        __syncthreads();
    }
}

// ---------- BN stats ----------
__global__ void bn_stats(const float* __restrict__ gamma, const float* __restrict__ beta){
    const int j=blockIdx.x, tid=threadIdx.x;
    __shared__ float red[256]; __shared__ float mean_s;
    float s=0.0f;
    for(int r=tid;r<BB;r+=256) s+=g_h[r*HH+j];
    red[tid]=s; __syncthreads();
    for(int o=128;o>0;o>>=1){ if(tid<o) red[tid]+=red[tid+o]; __syncthreads(); }
    if(tid==0) mean_s=red[0]*(1.0f/BB);
    __syncthreads();
    const float m=mean_s;
    float s2=0.0f;
    for(int r=tid;r<BB;r+=256){ float d=g_h[r*HH+j]-m; s2+=d*d; }
    red[tid]=s2; __syncthreads();
    for(int o=128;o>0;o>>=1){ if(tid<o) red[tid]+=red[tid+o]; __syncthreads(); }
    if(tid==0){ float var=red[0]*(1.0f/BB); float rstd=rsqrtf(var+1e-5f);
        g_scale[j]=rstd*gamma[j]; g_shift[j]=beta[j]-m*rstd*gamma[j]; }
}

// ---------- BN apply + LeakyReLU + FC + sigmoid ----------
__global__ void out_kernel(const float* __restrict__ fcw, const float* __restrict__ fcb,
                           float* __restrict__ out){
    const int lanei=threadIdx.x&31, wp=threadIdx.x>>5;
    const int b=blockIdx.x*4+wp;
    float acc=0.0f;
#pragma unroll
    for(int qq=0;qq<4;qq++){
        int j=lanei+qq*32;
        float v=fmaf(g_h[b*HH+j], g_scale[j], g_shift[j]);
        v=(v>=0.0f)?v:0.01f*v;
        acc=fmaf(v, fcw[j], acc);
    }
#pragma unroll
    for(int o=16;o>0;o>>=1) acc+=__shfl_xor_sync(0xffffffffu,acc,o);
    if(lanei==0) out[b]=sigm(acc+fcb[0]);
}

// ---------- launch ----------
extern "C" void kernel_launch(void* const* d_in, const int* in_sizes, int n_in,
                              void* d_out, int out_size){
    const float* x     = (const float*)d_in[0];
    const float* W_ih  = (const float*)d_in[1];
    const float* W_hh  = (const float*)d_in[2];
    const float* b_ih  = (const float*)d_in[3];
    const float* b_hh  = (const float*)d_in[4];
    const float* gamma = (const float*)d_in[5];
    const float* beta  = (const float*)d_in[6];
    const float* fc_w  = (const float*)d_in[7];
    const float* fc_b  = (const float*)d_in[8];
    float* out = (float*)d_out;

    cudaFuncSetAttribute(lstm_main, cudaFuncAttributeMaxDynamicSharedMemorySize, SMEM_DYN);
    lstm_main<<<BB/32, 512, SMEM_DYN>>>(x, W_ih, W_hh, b_ih, b_hh);
    bn_stats<<<HH, 256>>>(gamma, beta);
    out_kernel<<<BB/4, 128>>>(fc_w, fc_b, out);
}